// round 1
// baseline (speedup 1.0000x reference)
#include <cuda_runtime.h>
#include <math.h>

#define Bb 64
#define Nn 200
#define Hh 256
#define NHh 8
#define Gg 2
#define Ll 3
#define Ff 512
#define Dh 32
#define ROWS (Bb*Nn)            // 12800
#define HPH (NHh*Hh)            // 2048

// ---- output layout (floats) ----
#define OUT_POLICY 0
#define OUT_H      12800
#define OUT_C      29184
#define OUT_EMB    45568

// ---- scratch arena offsets (floats) ----
#define OFF_X    0
#define OFF_XP   3276800
#define OFF_ASRC 29491200
#define OFF_ADST 29593600
#define OFF_ATTN 29696000
#define OFF_MSGH 50176000
#define OFF_EMB  76390400
#define OFF_Q    79667200
#define OFF_K    82944000
#define OFF_V    86220800
#define OFF_CTX  89497600
#define OFF_T1   92774400
#define OFF_TMP  99328000
#define OFF_REF  102604800
#define OFF_HB   105881600
#define OFF_CB   105897984
#define OFF_QH   105914368
#define SCRATCH_TOTAL 105930752

__device__ float g_scratch[SCRATCH_TOTAL];

__device__ __forceinline__ float warp_sum(float v) {
#pragma unroll
    for (int o = 16; o > 0; o >>= 1) v += __shfl_xor_sync(0xffffffffu, v, o);
    return v;
}
__device__ __forceinline__ float warp_max(float v) {
#pragma unroll
    for (int o = 16; o > 0; o >>= 1) v = fmaxf(v, __shfl_xor_sync(0xffffffffu, v, o));
    return v;
}
__device__ __forceinline__ float sigmf(float x) { return 1.f / (1.f + __expf(-x)); }

// ============================================================================
// Generic fp32 GEMM: C[M,N] = A[M,K] @ B[K,N] (+bias, +relu)
// Requires M%64==0, N%64==0, K%16==0. flags: bit0 = bias, bit1 = relu.
// ============================================================================
__global__ void sgemm64(const float* __restrict__ A, const float* __restrict__ B,
                        const float* __restrict__ bias, float* __restrict__ C,
                        int M, int N, int K, int flags) {
    __shared__ float As[64][17];
    __shared__ float Bs[16][64];
    int tid = threadIdx.x;
    int tx = tid & 15, ty = tid >> 4;
    int tx4 = tx * 4, ty4 = ty * 4;
    int row0 = blockIdx.y * 64, col0 = blockIdx.x * 64;
    int la_row = tid >> 2, la_k = (tid & 3) * 4;
    int lb_k = tid >> 4, lb_n = (tid & 15) * 4;
    float acc[4][4] = {};
    for (int k0 = 0; k0 < K; k0 += 16) {
        float4 a4 = *(const float4*)&A[(size_t)(row0 + la_row) * K + k0 + la_k];
        As[la_row][la_k + 0] = a4.x;
        As[la_row][la_k + 1] = a4.y;
        As[la_row][la_k + 2] = a4.z;
        As[la_row][la_k + 3] = a4.w;
        *(float4*)&Bs[lb_k][lb_n] = *(const float4*)&B[(size_t)(k0 + lb_k) * N + col0 + lb_n];
        __syncthreads();
#pragma unroll
        for (int kk = 0; kk < 16; kk++) {
            float a0 = As[ty4 + 0][kk], a1 = As[ty4 + 1][kk];
            float a2 = As[ty4 + 2][kk], a3 = As[ty4 + 3][kk];
            float4 bb = *(float4*)&Bs[kk][tx4];
            acc[0][0] += a0 * bb.x; acc[0][1] += a0 * bb.y; acc[0][2] += a0 * bb.z; acc[0][3] += a0 * bb.w;
            acc[1][0] += a1 * bb.x; acc[1][1] += a1 * bb.y; acc[1][2] += a1 * bb.z; acc[1][3] += a1 * bb.w;
            acc[2][0] += a2 * bb.x; acc[2][1] += a2 * bb.y; acc[2][2] += a2 * bb.z; acc[2][3] += a2 * bb.w;
            acc[3][0] += a3 * bb.x; acc[3][1] += a3 * bb.y; acc[3][2] += a3 * bb.z; acc[3][3] += a3 * bb.w;
        }
        __syncthreads();
    }
    float4 bb = make_float4(0.f, 0.f, 0.f, 0.f);
    if (flags & 1) bb = *(const float4*)&bias[col0 + tx4];
#pragma unroll
    for (int i = 0; i < 4; i++) {
        int r = row0 + ty4 + i;
        float4 c = make_float4(acc[i][0] + bb.x, acc[i][1] + bb.y,
                               acc[i][2] + bb.z, acc[i][3] + bb.w);
        if (flags & 2) {
            c.x = fmaxf(c.x, 0.f); c.y = fmaxf(c.y, 0.f);
            c.z = fmaxf(c.z, 0.f); c.w = fmaxf(c.w, 0.f);
        }
        *(float4*)&C[(size_t)r * N + col0 + tx4] = c;
    }
}

// ============================================================================
// GAT: per-(b,n,h) attention coefficients a_src / a_dst (stored [B,NH,N])
// ============================================================================
__global__ void gat_coef(const float* __restrict__ xp, const float* __restrict__ att_src,
                         const float* __restrict__ att_dst, float* __restrict__ asrc,
                         float* __restrict__ adst, int g) {
    int row = blockIdx.x;
    int b = row / Nn, n = row % Nn;
    int h = threadIdx.x >> 5, lane = threadIdx.x & 31;
    const float* xr = xp + (size_t)row * HPH + h * Hh;
    const float* as = att_src + (size_t)(g * NHh + h) * Hh;
    const float* ad = att_dst + (size_t)(g * NHh + h) * Hh;
    float s1 = 0.f, s2 = 0.f;
    for (int d = lane; d < Hh; d += 32) {
        float xv = xr[d];
        s1 += xv * as[d];
        s2 += xv * ad[d];
    }
    s1 = warp_sum(s1);
    s2 = warp_sum(s2);
    if (!lane) {
        asrc[(b * NHh + h) * Nn + n] = s1;
        adst[(b * NHh + h) * Nn + n] = s2;
    }
}

// ============================================================================
// GAT masked softmax over sources i, per (b, target j, head h). attn[B,NH,j,i]
// ============================================================================
__global__ void gat_softmax(const float* __restrict__ asrc, const float* __restrict__ adst,
                            const int* __restrict__ adj, float* __restrict__ attn) {
    int j = blockIdx.x, b = blockIdx.y;
    __shared__ float am[Nn];
    __shared__ float Ps[NHh][Nn];
    int tid = threadIdx.x;
    if (tid < Nn)
        am[tid] = (tid == j || adj[(b * Nn + tid) * Nn + j] > 0) ? 1.f : 0.f;
    __syncthreads();
    int h = tid >> 5, lane = tid & 31;
    float ad = adst[(b * NHh + h) * Nn + j];
    const float* as = asrc + (b * NHh + h) * Nn;
    float* arow = attn + (size_t)((b * NHh + h) * Nn + j) * Nn;
    float m = -1e30f;
    for (int i = lane; i < Nn; i += 32) {
        float e = ad + as[i];
        e = e > 0.f ? e : 0.2f * e;        // leaky_relu(0.2)
        e = am[i] > 0.f ? e : -1e9f;
        Ps[h][i] = e;
        m = fmaxf(m, e);
    }
    m = warp_max(m);
    float s = 0.f;
    for (int i = lane; i < Nn; i += 32) {
        float e = __expf(Ps[h][i] - m);
        Ps[h][i] = e;
        s += e;
    }
    s = warp_sum(s);
    float inv = 1.f / s;
    for (int i = lane; i < Nn; i += 32) arow[i] = Ps[h][i] * inv;
}

// ============================================================================
// GAT message GEMM: msgh[b][j, c] = sum_i attn[b, c/256][j,i] * xp[b][i, c]
// Head is a function of the column tile (64 | 256). Bounds in j and K=200.
// grid (32 col-tiles, 4 row-tiles, B)
// ============================================================================
__global__ void gat_msg_gemm(const float* __restrict__ attn, const float* __restrict__ xp,
                             float* __restrict__ msgh) {
    int b = blockIdx.z, jt = blockIdx.y, ct = blockIdx.x;
    int h = ct >> 2;
    const float* A = attn + (size_t)(b * NHh + h) * Nn * Nn;
    const float* Bm = xp + (size_t)b * Nn * HPH;
    float* C = msgh + (size_t)b * Nn * HPH;
    int row0 = jt * 64, col0 = ct * 64;
    __shared__ float As[64][17];
    __shared__ float Bs[16][64];
    int tid = threadIdx.x;
    int tx = tid & 15, ty = tid >> 4;
    int tx4 = tx * 4, ty4 = ty * 4;
    int la_row = tid >> 2, la_k = (tid & 3) * 4;
    int lb_k = tid >> 4, lb_n = (tid & 15) * 4;
    float acc[4][4] = {};
    for (int k0 = 0; k0 < Nn; k0 += 16) {
        int ar = row0 + la_row;
#pragma unroll
        for (int t = 0; t < 4; t++) {
            int kk = k0 + la_k + t;
            As[la_row][la_k + t] = (ar < Nn && kk < Nn) ? A[ar * Nn + kk] : 0.f;
        }
        int br = k0 + lb_k;
        if (br < Nn)
            *(float4*)&Bs[lb_k][lb_n] = *(const float4*)&Bm[(size_t)br * HPH + col0 + lb_n];
        else {
            Bs[lb_k][lb_n + 0] = 0.f; Bs[lb_k][lb_n + 1] = 0.f;
            Bs[lb_k][lb_n + 2] = 0.f; Bs[lb_k][lb_n + 3] = 0.f;
        }
        __syncthreads();
#pragma unroll
        for (int kk = 0; kk < 16; kk++) {
            float a0 = As[ty4 + 0][kk], a1 = As[ty4 + 1][kk];
            float a2 = As[ty4 + 2][kk], a3 = As[ty4 + 3][kk];
            float4 bb = *(float4*)&Bs[kk][tx4];
            acc[0][0] += a0 * bb.x; acc[0][1] += a0 * bb.y; acc[0][2] += a0 * bb.z; acc[0][3] += a0 * bb.w;
            acc[1][0] += a1 * bb.x; acc[1][1] += a1 * bb.y; acc[1][2] += a1 * bb.z; acc[1][3] += a1 * bb.w;
            acc[2][0] += a2 * bb.x; acc[2][1] += a2 * bb.y; acc[2][2] += a2 * bb.z; acc[2][3] += a2 * bb.w;
            acc[3][0] += a3 * bb.x; acc[3][1] += a3 * bb.y; acc[3][2] += a3 * bb.z; acc[3][3] += a3 * bb.w;
        }
        __syncthreads();
    }
#pragma unroll
    for (int i = 0; i < 4; i++) {
        int r = row0 + ty4 + i;
        if (r < Nn)
            *(float4*)&C[(size_t)r * HPH + col0 + tx4] =
                make_float4(acc[i][0], acc[i][1], acc[i][2], acc[i][3]);
    }
}

// x[row,d] += relu( mean_h msgh[row, h*256+d] + gat_bias[g,d] )
__global__ void gat_msg_reduce(const float* __restrict__ msgh, const float* __restrict__ gbias,
                               int g, float* __restrict__ x) {
    int row = blockIdx.x, d = threadIdx.x;
    const float* mr = msgh + (size_t)row * HPH;
    float s = 0.f;
#pragma unroll
    for (int h = 0; h < NHh; h++) s += mr[h * Hh + d];
    s = s * (1.f / NHh) + gbias[g * Hh + d];
    x[row * Hh + d] += fmaxf(s, 0.f);
}

// ============================================================================
// out = LN(a + (relu_b ? relu(bsrc) : bsrc)) * sb[0,:] + sb[1,:]  per row of H
// ============================================================================
__global__ void add_ln(const float* __restrict__ a, const float* __restrict__ bsrc,
                       float* __restrict__ outp, const float* __restrict__ sb, int relu_b) {
    int row = blockIdx.x, d = threadIdx.x;
    float bv = bsrc[(size_t)row * Hh + d];
    if (relu_b) bv = fmaxf(bv, 0.f);
    float v = a[(size_t)row * Hh + d] + bv;
    __shared__ float sw[8], sw2[8];
    float s = warp_sum(v), s2 = warp_sum(v * v);
    int w = d >> 5, lane = d & 31;
    if (!lane) { sw[w] = s; sw2[w] = s2; }
    __syncthreads();
    float ts = 0.f, ts2 = 0.f;
#pragma unroll
    for (int i = 0; i < 8; i++) { ts += sw[i]; ts2 += sw2[i]; }
    float mean = ts * (1.f / Hh);
    float var = ts2 * (1.f / Hh) - mean * mean;
    outp[(size_t)row * Hh + d] = (v - mean) * rsqrtf(var + 1e-5f) * sb[d] + sb[Hh + d];
}

// ============================================================================
// Fused masked MHA for one (b, head): smem Q/K/V slabs, softmax, ctx.
// grid (NH, B), 256 threads, 84000B dynamic smem.
// ============================================================================
__global__ void mha_attn(const float* __restrict__ q, const float* __restrict__ k,
                         const float* __restrict__ v, const int* __restrict__ adj,
                         float* __restrict__ ctx) {
    int h = blockIdx.x, b = blockIdx.y;
    extern __shared__ float sm[];
    float* Qs = sm;                 // [200][32]
    float* Ks = Qs + Nn * Dh;       // [200][33] (padded)
    float* Vs = Ks + Nn * 33;       // [200][32]
    float* Ps = Vs + Nn * Dh;       // [8][200]
    int tid = threadIdx.x;
    for (int idx = tid; idx < Nn * Dh; idx += 256) {
        int i = idx >> 5, d = idx & 31;
        int gi = (b * Nn + i) * Hh + h * Dh + d;
        Qs[i * Dh + d] = q[gi];
        Ks[i * 33 + d] = k[gi];
        Vs[i * Dh + d] = v[gi];
    }
    __syncthreads();
    int w = tid >> 5, lane = tid & 31;
    float* P = Ps + w * Nn;
    const float scale = 0.17677669529663687f;   // 1/sqrt(32)
    for (int j = w; j < Nn; j += 8) {
        const float* qj = Qs + j * Dh;
        const int* arow = adj + (b * Nn + j) * Nn;
        float m = -1e30f;
        for (int i = lane; i < Nn; i += 32) {
            const float* kr = Ks + i * 33;
            float s = 0.f;
#pragma unroll
            for (int d = 0; d < Dh; d++) s += qj[d] * kr[d];
            s = arow[i] > 0 ? s * scale : -1e9f;
            P[i] = s;
            m = fmaxf(m, s);
        }
        m = warp_max(m);
        float sum = 0.f;
        for (int i = lane; i < Nn; i += 32) {
            float e = __expf(P[i] - m);
            P[i] = e;
            sum += e;
        }
        sum = warp_sum(sum);
        float inv = 1.f / sum;
        __syncwarp();
        float acc = 0.f;
        for (int i = 0; i < Nn; i++) acc += P[i] * Vs[i * Dh + lane];
        ctx[(b * Nn + j) * Hh + h * Dh + lane] = acc * inv;
        __syncwarp();
    }
}

// ============================================================================
// LSTM cell (B=64 blocks x 256 threads). Writes h,c to scratch AND d_out.
// ============================================================================
__global__ void lstm_kernel(const float* __restrict__ xin, const float* __restrict__ hin,
                            const float* __restrict__ cin, const float* __restrict__ Wih,
                            const float* __restrict__ Whh, const float* __restrict__ bias,
                            float* __restrict__ gh, float* __restrict__ gc,
                            float* __restrict__ out) {
    int b = blockIdx.x, tid = threadIdx.x;
    __shared__ float xs[Hh], hs[Hh], gsh[4 * Hh];
    xs[tid] = xin[b * Hh + tid];
    hs[tid] = hin[b * Hh + tid];
    __syncthreads();
    for (int r = tid; r < 4 * Hh; r += Hh) {
        const float* wi = Wih + (size_t)r * Hh;
        const float* wh = Whh + (size_t)r * Hh;
        float s = bias[r];
        for (int d = 0; d < Hh; d++) s += xs[d] * wi[d] + hs[d] * wh[d];
        gsh[r] = s;
    }
    __syncthreads();
    float ig = gsh[tid], fg = gsh[Hh + tid], gg = gsh[2 * Hh + tid], og = gsh[3 * Hh + tid];
    float c = sigmf(fg) * cin[b * Hh + tid] + sigmf(ig) * tanhf(gg);
    float hv = sigmf(og) * tanhf(c);
    gh[b * Hh + tid] = hv;
    gc[b * Hh + tid] = c;
    out[OUT_H + b * Hh + tid] = hv;
    out[OUT_C + b * Hh + tid] = c;
}

// ============================================================================
// Pointer head: u = tanh(ref + qh) @ v, masked softmax over N -> policy
// ============================================================================
__global__ void ptr_kernel(const float* __restrict__ refb, const float* __restrict__ qh,
                           const float* __restrict__ vvec, const int* __restrict__ mask,
                           float* __restrict__ out) {
    int b = blockIdx.x, tid = threadIdx.x;
    __shared__ float us[Nn];
    __shared__ float red[8];
    int w = tid >> 5, lane = tid & 31;
    const float* qv = qh + b * Hh;
    for (int n = w; n < Nn; n += 8) {
        const float* r = refb + (size_t)(b * Nn + n) * Hh;
        float s = 0.f;
        for (int d = lane; d < Hh; d += 32) s += tanhf(r[d] + qv[d]) * vvec[d];
        s = warp_sum(s);
        if (!lane) us[n] = s;
    }
    __syncthreads();
    float vvv = -1e30f;
    if (tid < Nn) vvv = mask[b * Nn + tid] > 0 ? us[tid] : -1e9f;
    float m = warp_max(vvv);
    if (!lane) red[w] = m;
    __syncthreads();
    float bm = red[0];
#pragma unroll
    for (int i = 1; i < 8; i++) bm = fmaxf(bm, red[i]);
    float e = (tid < Nn) ? __expf(vvv - bm) : 0.f;
    float s = warp_sum(e);
    __syncthreads();
    if (!lane) red[w] = s;
    __syncthreads();
    float bs = 0.f;
#pragma unroll
    for (int i = 0; i < 8; i++) bs += red[i];
    if (tid < Nn) out[OUT_POLICY + b * Nn + tid] = e / bs;
}

__global__ void copy_kernel(const float* __restrict__ src, float* __restrict__ dst) {
    int i = blockIdx.x * 256 + threadIdx.x;
    dst[i] = src[i];
}

// ============================================================================
// Launch
// ============================================================================
extern "C" void kernel_launch(void* const* d_in, const int* in_sizes, int n_in,
                              void* d_out, int out_size) {
    const float* enc        = (const float*)d_in[0];
    const float* dec_input  = (const float*)d_in[1];
    const float* dec_h      = (const float*)d_in[2];
    const float* dec_c      = (const float*)d_in[3];
    const float* gat_W      = (const float*)d_in[4];
    const float* gat_asrc_w = (const float*)d_in[5];
    const float* gat_adst_w = (const float*)d_in[6];
    const float* gat_bias   = (const float*)d_in[7];
    const float* gat_ln     = (const float*)d_in[8];
    const float* attn_W     = (const float*)d_in[9];
    const float* attn_b     = (const float*)d_in[10];
    const float* ln1        = (const float*)d_in[11];
    const float* ffn_W1     = (const float*)d_in[12];
    const float* ffn_b1     = (const float*)d_in[13];
    const float* ffn_W2     = (const float*)d_in[14];
    const float* ffn_b2     = (const float*)d_in[15];
    const float* ln2        = (const float*)d_in[16];
    const float* lstm_Wih   = (const float*)d_in[17];
    const float* lstm_Whh   = (const float*)d_in[18];
    const float* lstm_b     = (const float*)d_in[19];
    const float* ptr_Wref   = (const float*)d_in[20];
    const float* ptr_Wq     = (const float*)d_in[21];
    const float* ptr_v      = (const float*)d_in[22];
    const int*   adj        = (const int*)d_in[23];
    const int*   mask       = (const int*)d_in[24];
    float* out = (float*)d_out;

    float* S = nullptr;
    cudaGetSymbolAddress((void**)&S, g_scratch);
    float* x    = S + OFF_X;
    float* xp   = S + OFF_XP;
    float* asrc = S + OFF_ASRC;
    float* adst = S + OFF_ADST;
    float* attn = S + OFF_ATTN;
    float* msgh = S + OFF_MSGH;
    float* emb  = S + OFF_EMB;
    float* q    = S + OFF_Q;
    float* k    = S + OFF_K;
    float* v    = S + OFF_V;
    float* ctx  = S + OFF_CTX;
    float* t1   = S + OFF_T1;
    float* tmp  = S + OFF_TMP;
    float* refb = S + OFF_REF;
    float* gh   = S + OFF_HB;
    float* gc   = S + OFF_CB;
    float* qh   = S + OFF_QH;

    cudaFuncSetAttribute(mha_attn, cudaFuncAttributeMaxDynamicSharedMemorySize, 84000);

    // x = enc_inputs
    copy_kernel<<<12800, 256>>>(enc, x);

    // ---- GAT stack ----
    for (int g = 0; g < Gg; g++) {
        sgemm64<<<dim3(32, 200), 256>>>(x, gat_W + (size_t)g * Hh * HPH, nullptr, xp,
                                        ROWS, HPH, Hh, 0);
        gat_coef<<<ROWS, 256>>>(xp, gat_asrc_w, gat_adst_w, asrc, adst, g);
        gat_softmax<<<dim3(Nn, Bb), 256>>>(asrc, adst, adj, attn);
        gat_msg_gemm<<<dim3(32, 4, Bb), 256>>>(attn, xp, msgh);
        gat_msg_reduce<<<ROWS, Hh>>>(msgh, gat_bias, g, x);
    }
    add_ln<<<ROWS, Hh>>>(enc, x, emb, gat_ln, 1);

    // ---- Transformer encoder ----
    for (int l = 0; l < Ll; l++) {
        const float* W = attn_W + (size_t)l * 4 * Hh * Hh;
        const float* bq = attn_b + (size_t)l * 4 * Hh;
        sgemm64<<<dim3(4, 200), 256>>>(emb, W,               bq,          q, ROWS, Hh, Hh, 1);
        sgemm64<<<dim3(4, 200), 256>>>(emb, W + Hh * Hh,     bq + Hh,     k, ROWS, Hh, Hh, 1);
        sgemm64<<<dim3(4, 200), 256>>>(emb, W + 2 * Hh * Hh, bq + 2 * Hh, v, ROWS, Hh, Hh, 1);
        mha_attn<<<dim3(NHh, Bb), 256, 84000>>>(q, k, v, adj, ctx);
        sgemm64<<<dim3(4, 200), 256>>>(ctx, W + 3 * Hh * Hh, bq + 3 * Hh, tmp, ROWS, Hh, Hh, 1);
        add_ln<<<ROWS, Hh>>>(emb, tmp, emb, ln1 + (size_t)l * 2 * Hh, 0);
        sgemm64<<<dim3(8, 200), 256>>>(emb, ffn_W1 + (size_t)l * Hh * Ff, ffn_b1 + (size_t)l * Ff,
                                       t1, ROWS, Ff, Hh, 3);
        sgemm64<<<dim3(4, 200), 256>>>(t1, ffn_W2 + (size_t)l * Ff * Hh, ffn_b2 + (size_t)l * Hh,
                                       tmp, ROWS, Hh, Ff, 1);
        add_ln<<<ROWS, Hh>>>(emb, tmp, emb, ln2 + (size_t)l * 2 * Hh, 0);
    }

    // ---- LSTM cell + pointer head ----
    lstm_kernel<<<Bb, Hh>>>(dec_input, dec_h, dec_c, lstm_Wih, lstm_Whh, lstm_b, gh, gc, out);
    sgemm64<<<dim3(4, 200), 256>>>(emb, ptr_Wref, nullptr, refb, ROWS, Hh, Hh, 0);
    sgemm64<<<dim3(4, 1), 256>>>(gh, ptr_Wq, nullptr, qh, Bb, Hh, Hh, 0);
    ptr_kernel<<<Bb, 256>>>(refb, qh, ptr_v, mask, out);

    // ---- emit emb ----
    copy_kernel<<<12800, 256>>>(emb, out + OUT_EMB);
}

// round 8
// speedup vs baseline: 1.6278x; 1.6278x over previous
#include <cuda_runtime.h>
#include <math.h>
#include <stdint.h>

#define Bb 64
#define Nn 200
#define Hh 256
#define NHh 8
#define Gg 2
#define Ll 3
#define Ff 512
#define ROWS 12800
#define HPH 2048

// ---- output layout (floats) ----
#define OUT_POLICY 0
#define OUT_H      12800
#define OUT_C      29184
#define OUT_EMB    45568

// ---- scratch arena offsets (floats) ----
#define OFF_X    0
#define OFF_XP   3276800
#define OFF_ASRC 29491200
#define OFF_ADST 29593600
#define OFF_ATTN 29696000
#define OFF_MSGH 50176000
#define OFF_EMB  76390400
#define OFF_QKV  79667200           // [12800, 768]
#define OFF_CTX  89497600
#define OFF_T1   92774400
#define OFF_TMP  99328000
#define OFF_REF  102604800
#define OFF_HB   105881600
#define OFF_CB   105897984
#define OFF_QH   105914368
#define SCRATCH_TOTAL 105930752

__device__ float g_scratch[SCRATCH_TOTAL];

__device__ __forceinline__ float warp_sum(float v) {
#pragma unroll
    for (int o = 16; o > 0; o >>= 1) v += __shfl_xor_sync(0xffffffffu, v, o);
    return v;
}
__device__ __forceinline__ float warp_max(float v) {
#pragma unroll
    for (int o = 16; o > 0; o >>= 1) v = fmaxf(v, __shfl_xor_sync(0xffffffffu, v, o));
    return v;
}
__device__ __forceinline__ float sigmf(float x) { return 1.f / (1.f + __expf(-x)); }
__device__ __forceinline__ float tf32r(float x) {
    float y;
    asm("cvt.rna.tf32.f32 %0, %1;" : "=f"(y) : "f"(x));
    return y;
}

// mma.sync m16n8k8 tf32 (baseline sm_80+ instruction — valid on compute_103)
__device__ __forceinline__ void mma8(float* c, const uint32_t* a, const uint32_t* b) {
    asm volatile(
        "mma.sync.aligned.m16n8k8.row.col.f32.tf32.tf32.f32 "
        "{%0,%1,%2,%3}, {%4,%5,%6,%7}, {%8,%9}, {%0,%1,%2,%3};"
        : "+f"(c[0]), "+f"(c[1]), "+f"(c[2]), "+f"(c[3])
        : "r"(a[0]), "r"(a[1]), "r"(a[2]), "r"(a[3]), "r"(b[0]), "r"(b[1]));
}

// ============================================================================
// tf32 mma.sync GEMM core.  C tile [128,128] = A[row0:+128, :K] @ B[:K, n-tile]
// A: K-major (lda); zero-fill rows>=M, k>=K (K%4==0 required — holds: 200/256/512).
// Bp: pre-offset to tile col base, [K, >=128] with stride ldb.
// Cp/biasp pre-offset to tile col base. flags: 1=bias, 2=relu.
// 8 warps; warp (wy=wid&3, wx=wid>>2) owns rows wy*32..+32, cols wx*64..+64.
// Smem: A and B both stored [k][row/col] with pad 132 -> conflict-free frags.
// ============================================================================
#define PAD 132

__device__ __forceinline__ void mm_core(
    const float* __restrict__ A, int lda, int row0, int M, int K,
    const float* __restrict__ Bp, int ldb,
    const float* __restrict__ biasp, float* __restrict__ Cp, int ldc, int flags)
{
    __shared__ float As[2][16][PAD];
    __shared__ float Bs[2][16][PAD];
    int tid = threadIdx.x, lane = tid & 31, wid = tid >> 5;
    int wy = wid & 3, wx = wid >> 2;
    int g = lane >> 2, tg = lane & 3;

    const int T = (K + 15) >> 4;
    const float4 z4 = make_float4(0.f, 0.f, 0.f, 0.f);

    float c[2][8][4];
#pragma unroll
    for (int ma = 0; ma < 2; ma++)
#pragma unroll
        for (int na = 0; na < 8; na++)
#pragma unroll
            for (int q = 0; q < 4; q++) c[ma][na][q] = 0.f;

    // loader mapping (2 float4 each for A and B)
    int a_row[2], a_kc[2], b_kk[2], b_nb[2];
#pragma unroll
    for (int i = 0; i < 2; i++) {
        int idx = tid + i * 256;
        a_row[i] = idx >> 2;          // 0..127
        a_kc[i] = (idx & 3) * 4;      // 0,4,8,12
        b_kk[i] = idx >> 5;           // 0..15
        b_nb[i] = (idx & 31) * 4;     // 0..124
    }

    float4 ra[2], rb[2];

#define LOADG(t)                                                                     \
    {                                                                                \
        int k0 = (t) * 16;                                                           \
        _Pragma("unroll")                                                            \
        for (int i = 0; i < 2; i++) {                                                \
            ra[i] = (row0 + a_row[i] < M && k0 + a_kc[i] < K)                        \
                ? *(const float4*)&A[(size_t)(row0 + a_row[i]) * lda + k0 + a_kc[i]] \
                : z4;                                                                \
            rb[i] = (k0 + b_kk[i] < K)                                               \
                ? *(const float4*)&Bp[(size_t)(k0 + b_kk[i]) * ldb + b_nb[i]]        \
                : z4;                                                                \
        }                                                                            \
    }
#define STS(s)                                                                       \
    {                                                                                \
        _Pragma("unroll")                                                            \
        for (int i = 0; i < 2; i++) {                                                \
            As[s][a_kc[i] + 0][a_row[i]] = tf32r(ra[i].x);                           \
            As[s][a_kc[i] + 1][a_row[i]] = tf32r(ra[i].y);                           \
            As[s][a_kc[i] + 2][a_row[i]] = tf32r(ra[i].z);                           \
            As[s][a_kc[i] + 3][a_row[i]] = tf32r(ra[i].w);                           \
            float4 t4 = make_float4(tf32r(rb[i].x), tf32r(rb[i].y),                  \
                                    tf32r(rb[i].z), tf32r(rb[i].w));                 \
            *(float4*)&Bs[s][b_kk[i]][b_nb[i]] = t4;                                 \
        }                                                                            \
    }

    LOADG(0)
    STS(0)
    __syncthreads();

    for (int t = 0; t < T; t++) {
        int s = t & 1;
        if (t + 1 < T) LOADG(t + 1)

#pragma unroll
        for (int ks = 0; ks < 2; ks++) {
            int kb = ks * 8;
            uint32_t afr[2][4], bfr[8][2];
#pragma unroll
            for (int ma = 0; ma < 2; ma++) {
                int r = wy * 32 + ma * 16 + g;
                afr[ma][0] = __float_as_uint(As[s][kb + tg][r]);
                afr[ma][1] = __float_as_uint(As[s][kb + tg][r + 8]);
                afr[ma][2] = __float_as_uint(As[s][kb + tg + 4][r]);
                afr[ma][3] = __float_as_uint(As[s][kb + tg + 4][r + 8]);
            }
#pragma unroll
            for (int na = 0; na < 8; na++) {
                int col = wx * 64 + na * 8 + g;
                bfr[na][0] = __float_as_uint(Bs[s][kb + tg][col]);
                bfr[na][1] = __float_as_uint(Bs[s][kb + tg + 4][col]);
            }
#pragma unroll
            for (int ma = 0; ma < 2; ma++)
#pragma unroll
                for (int na = 0; na < 8; na++) mma8(c[ma][na], afr[ma], bfr[na]);
        }

        if (t + 1 < T) STS(s ^ 1)
        __syncthreads();
    }

    // epilogue
#pragma unroll
    for (int ma = 0; ma < 2; ma++) {
        int r = row0 + wy * 32 + ma * 16 + g;
#pragma unroll
        for (int na = 0; na < 8; na++) {
            int colb = wx * 64 + na * 8 + tg * 2;
            float b0 = 0.f, b1 = 0.f;
            if (flags & 1) { b0 = biasp[colb]; b1 = biasp[colb + 1]; }
            float v0 = c[ma][na][0] + b0, v1 = c[ma][na][1] + b1;
            float v2 = c[ma][na][2] + b0, v3 = c[ma][na][3] + b1;
            if (flags & 2) {
                v0 = fmaxf(v0, 0.f); v1 = fmaxf(v1, 0.f);
                v2 = fmaxf(v2, 0.f); v3 = fmaxf(v3, 0.f);
            }
            if (r < M)     *(float2*)&Cp[(size_t)r * ldc + colb]       = make_float2(v0, v1);
            if (r + 8 < M) *(float2*)&Cp[(size_t)(r + 8) * ldc + colb] = make_float2(v2, v3);
        }
    }
#undef LOADG
#undef STS
}

// Regular GEMM: B may be a sequence of [K, bsplit] matrices (bsplit == ldb).
__global__ void __launch_bounds__(256)
mm_gemm(const float* __restrict__ A, int lda, const float* __restrict__ B, int ldb,
        int bsplit, const float* __restrict__ bias, float* __restrict__ C, int ldc,
        int M, int K, int flags) {
    int n0 = blockIdx.x * 128;
    int row0 = blockIdx.y * 128;
    const float* Bp = B + (size_t)(n0 / bsplit) * K * bsplit + (n0 % bsplit);
    mm_core(A, lda, row0, M, K, Bp, ldb,
            (flags & 1) ? bias + n0 : nullptr, C + n0, ldc, flags);
}

// GAT message GEMM: per (b,h): msg[j, d] = sum_i attn[b,h,j,i] * xp[b, i, h*256+d]
__global__ void __launch_bounds__(256)
mm_msg_gemm(const float* __restrict__ attn, const float* __restrict__ xp,
            float* __restrict__ msgh) {
    int z = blockIdx.z;
    int b = z >> 3, h = z & 7;
    int n0 = blockIdx.x * 128;
    int row0 = blockIdx.y * 128;
    const float* A = attn + (size_t)z * Nn * Nn;
    const float* Bp = xp + (size_t)b * Nn * HPH + h * Hh + n0;
    float* Cp = msgh + (size_t)b * Nn * HPH + h * Hh + n0;
    mm_core(A, Nn, row0, Nn, Nn, Bp, HPH, nullptr, Cp, HPH, 0);
}

// ============================================================================
// GAT coefficient / softmax / reduce
// ============================================================================
__global__ void gat_coef(const float* __restrict__ xp, const float* __restrict__ att_src,
                         const float* __restrict__ att_dst, float* __restrict__ asrc,
                         float* __restrict__ adst, int g) {
    int row = blockIdx.x;
    int b = row / Nn, n = row % Nn;
    int h = threadIdx.x >> 5, lane = threadIdx.x & 31;
    const float* xr = xp + (size_t)row * HPH + h * Hh;
    const float* as = att_src + (size_t)(g * NHh + h) * Hh;
    const float* ad = att_dst + (size_t)(g * NHh + h) * Hh;
    float s1 = 0.f, s2 = 0.f;
    for (int d = lane; d < Hh; d += 32) {
        float xv = xr[d];
        s1 += xv * as[d];
        s2 += xv * ad[d];
    }
    s1 = warp_sum(s1);
    s2 = warp_sum(s2);
    if (!lane) {
        asrc[(b * NHh + h) * Nn + n] = s1;
        adst[(b * NHh + h) * Nn + n] = s2;
    }
}

__global__ void gat_softmax(const float* __restrict__ asrc, const float* __restrict__ adst,
                            const int* __restrict__ adj, float* __restrict__ attn) {
    int j = blockIdx.x, b = blockIdx.y;
    __shared__ float am[Nn];
    __shared__ float Ps[NHh][Nn];
    int tid = threadIdx.x;
    if (tid < Nn)
        am[tid] = (tid == j || adj[(b * Nn + tid) * Nn + j] > 0) ? 1.f : 0.f;
    __syncthreads();
    int h = tid >> 5, lane = tid & 31;
    float ad = adst[(b * NHh + h) * Nn + j];
    const float* as = asrc + (b * NHh + h) * Nn;
    float* arow = attn + (size_t)((b * NHh + h) * Nn + j) * Nn;
    float m = -1e30f;
    for (int i = lane; i < Nn; i += 32) {
        float e = ad + as[i];
        e = e > 0.f ? e : 0.2f * e;        // leaky_relu(0.2)
        e = am[i] > 0.f ? e : -1e9f;
        Ps[h][i] = e;
        m = fmaxf(m, e);
    }
    m = warp_max(m);
    float s = 0.f;
    for (int i = lane; i < Nn; i += 32) {
        float e = __expf(Ps[h][i] - m);
        Ps[h][i] = e;
        s += e;
    }
    s = warp_sum(s);
    float inv = 1.f / s;
    for (int i = lane; i < Nn; i += 32) arow[i] = Ps[h][i] * inv;
}

__global__ void gat_msg_reduce(const float* __restrict__ msgh, const float* __restrict__ gbias,
                               int g, float* __restrict__ x) {
    int row = blockIdx.x, d = threadIdx.x;
    const float* mr = msgh + (size_t)row * HPH;
    float s = 0.f;
#pragma unroll
    for (int h = 0; h < NHh; h++) s += mr[h * Hh + d];
    s = s * (1.f / NHh) + gbias[g * Hh + d];
    x[row * Hh + d] += fmaxf(s, 0.f);
}

// ============================================================================
// add + LayerNorm
// ============================================================================
__global__ void add_ln(const float* __restrict__ a, const float* __restrict__ bsrc,
                       float* __restrict__ outp, const float* __restrict__ sb, int relu_b) {
    int row = blockIdx.x, d = threadIdx.x;
    float bv = bsrc[(size_t)row * Hh + d];
    if (relu_b) bv = fmaxf(bv, 0.f);
    float v = a[(size_t)row * Hh + d] + bv;
    __shared__ float sw[8], sw2[8];
    float s = warp_sum(v), s2 = warp_sum(v * v);
    int w = d >> 5, lane = d & 31;
    if (!lane) { sw[w] = s; sw2[w] = s2; }
    __syncthreads();
    float ts = 0.f, ts2 = 0.f;
#pragma unroll
    for (int i = 0; i < 8; i++) { ts += sw[i]; ts2 += sw2[i]; }
    float mean = ts * (1.f / Hh);
    float var = ts2 * (1.f / Hh) - mean * mean;
    outp[(size_t)row * Hh + d] = (v - mean) * rsqrtf(var + 1e-5f) * sb[d] + sb[Hh + d];
}

// ============================================================================
// Fused masked MHA (reads fused qkv buffer [rows, 768])
// ============================================================================
__global__ void mha_attn(const float* __restrict__ qkv, const int* __restrict__ adj,
                         float* __restrict__ ctx) {
    int h = blockIdx.x, b = blockIdx.y;
    extern __shared__ float sm[];
    float* Qs = sm;
    float* Ks = Qs + Nn * 32;
    float* Vs = Ks + Nn * 33;
    float* Ps = Vs + Nn * 32;
    int tid = threadIdx.x;
    for (int idx = tid; idx < Nn * 32; idx += 256) {
        int i = idx >> 5, d = idx & 31;
        int gi = (b * Nn + i) * 768 + h * 32 + d;
        Qs[i * 32 + d] = qkv[gi];
        Ks[i * 33 + d] = qkv[gi + 256];
        Vs[i * 32 + d] = qkv[gi + 512];
    }
    __syncthreads();
    int w = tid >> 5, lane = tid & 31;
    float* P = Ps + w * Nn;
    const float scale = 0.17677669529663687f;   // 1/sqrt(32)
    for (int j = w; j < Nn; j += 8) {
        const float* qj = Qs + j * 32;
        const int* arow = adj + (b * Nn + j) * Nn;
        float m = -1e30f;
        for (int i = lane; i < Nn; i += 32) {
            const float* kr = Ks + i * 33;
            float s = 0.f;
#pragma unroll
            for (int d = 0; d < 32; d++) s += qj[d] * kr[d];
            s = arow[i] > 0 ? s * scale : -1e9f;
            P[i] = s;
            m = fmaxf(m, s);
        }
        m = warp_max(m);
        float sum = 0.f;
        for (int i = lane; i < Nn; i += 32) {
            float e = __expf(P[i] - m);
            P[i] = e;
            sum += e;
        }
        sum = warp_sum(sum);
        float inv = 1.f / sum;
        __syncwarp();
        float acc = 0.f;
        for (int i = 0; i < Nn; i++) acc += P[i] * Vs[i * 32 + lane];
        ctx[(b * Nn + j) * Hh + h * 32 + lane] = acc * inv;
        __syncwarp();
    }
}

// ============================================================================
// LSTM cell
// ============================================================================
__global__ void lstm_kernel(const float* __restrict__ xin, const float* __restrict__ hin,
                            const float* __restrict__ cin, const float* __restrict__ Wih,
                            const float* __restrict__ Whh, const float* __restrict__ bias,
                            float* __restrict__ gh, float* __restrict__ gc,
                            float* __restrict__ out) {
    int b = blockIdx.x, tid = threadIdx.x;
    __shared__ float xs[Hh], hs[Hh], gsh[4 * Hh];
    xs[tid] = xin[b * Hh + tid];
    hs[tid] = hin[b * Hh + tid];
    __syncthreads();
    for (int r = tid; r < 4 * Hh; r += Hh) {
        const float* wi = Wih + (size_t)r * Hh;
        const float* wh = Whh + (size_t)r * Hh;
        float s = bias[r];
        for (int d = 0; d < Hh; d++) s += xs[d] * wi[d] + hs[d] * wh[d];
        gsh[r] = s;
    }
    __syncthreads();
    float ig = gsh[tid], fg = gsh[Hh + tid], gg = gsh[2 * Hh + tid], og = gsh[3 * Hh + tid];
    float c = sigmf(fg) * cin[b * Hh + tid] + sigmf(ig) * tanhf(gg);
    float hv = sigmf(og) * tanhf(c);
    gh[b * Hh + tid] = hv;
    gc[b * Hh + tid] = c;
    out[OUT_H + b * Hh + tid] = hv;
    out[OUT_C + b * Hh + tid] = c;
}

// ============================================================================
// Pointer head
// ============================================================================
__global__ void ptr_kernel(const float* __restrict__ refb, const float* __restrict__ qh,
                           const float* __restrict__ vvec, const int* __restrict__ mask,
                           float* __restrict__ out) {
    int b = blockIdx.x, tid = threadIdx.x;
    __shared__ float us[Nn];
    __shared__ float red[8];
    int w = tid >> 5, lane = tid & 31;
    const float* qv = qh + b * Hh;
    for (int n = w; n < Nn; n += 8) {
        const float* r = refb + (size_t)(b * Nn + n) * Hh;
        float s = 0.f;
        for (int d = lane; d < Hh; d += 32) s += tanhf(r[d] + qv[d]) * vvec[d];
        s = warp_sum(s);
        if (!lane) us[n] = s;
    }
    __syncthreads();
    float vvv = -1e30f;
    if (tid < Nn) vvv = mask[b * Nn + tid] > 0 ? us[tid] : -1e9f;
    float m = warp_max(vvv);
    if (!lane) red[w] = m;
    __syncthreads();
    float bm = red[0];
#pragma unroll
    for (int i = 1; i < 8; i++) bm = fmaxf(bm, red[i]);
    float e = (tid < Nn) ? __expf(vvv - bm) : 0.f;
    float s = warp_sum(e);
    __syncthreads();
    if (!lane) red[w] = s;
    __syncthreads();
    float bs = 0.f;
#pragma unroll
    for (int i = 0; i < 8; i++) bs += red[i];
    if (tid < Nn) out[OUT_POLICY + b * Nn + tid] = e / bs;
}

__global__ void copy_kernel(const float* __restrict__ src, float* __restrict__ dst) {
    int i = blockIdx.x * 256 + threadIdx.x;
    dst[i] = src[i];
}

// ============================================================================
// Launch
// ============================================================================
extern "C" void kernel_launch(void* const* d_in, const int* in_sizes, int n_in,
                              void* d_out, int out_size) {
    const float* enc        = (const float*)d_in[0];
    const float* dec_input  = (const float*)d_in[1];
    const float* dec_h      = (const float*)d_in[2];
    const float* dec_c      = (const float*)d_in[3];
    const float* gat_W      = (const float*)d_in[4];
    const float* gat_asrc_w = (const float*)d_in[5];
    const float* gat_adst_w = (const float*)d_in[6];
    const float* gat_bias   = (const float*)d_in[7];
    const float* gat_ln     = (const float*)d_in[8];
    const float* attn_W     = (const float*)d_in[9];
    const float* attn_b     = (const float*)d_in[10];
    const float* ln1        = (const float*)d_in[11];
    const float* ffn_W1     = (const float*)d_in[12];
    const float* ffn_b1     = (const float*)d_in[13];
    const float* ffn_W2     = (const float*)d_in[14];
    const float* ffn_b2     = (const float*)d_in[15];
    const float* ln2        = (const float*)d_in[16];
    const float* lstm_Wih   = (const float*)d_in[17];
    const float* lstm_Whh   = (const float*)d_in[18];
    const float* lstm_b     = (const float*)d_in[19];
    const float* ptr_Wref   = (const float*)d_in[20];
    const float* ptr_Wq     = (const float*)d_in[21];
    const float* ptr_v      = (const float*)d_in[22];
    const int*   adj        = (const int*)d_in[23];
    const int*   mask       = (const int*)d_in[24];
    float* out = (float*)d_out;

    float* S = nullptr;
    cudaGetSymbolAddress((void**)&S, g_scratch);
    float* x    = S + OFF_X;
    float* xp   = S + OFF_XP;
    float* asrc = S + OFF_ASRC;
    float* adst = S + OFF_ADST;
    float* attn = S + OFF_ATTN;
    float* msgh = S + OFF_MSGH;
    float* emb  = S + OFF_EMB;
    float* qkv  = S + OFF_QKV;
    float* ctx  = S + OFF_CTX;
    float* t1   = S + OFF_T1;
    float* tmp  = S + OFF_TMP;
    float* refb = S + OFF_REF;
    float* gh   = S + OFF_HB;
    float* gc   = S + OFF_CB;
    float* qh   = S + OFF_QH;

    cudaFuncSetAttribute(mha_attn, cudaFuncAttributeMaxDynamicSharedMemorySize, 84000);

    // x = enc_inputs
    copy_kernel<<<12800, 256>>>(enc, x);

    // ---- GAT stack ----
    for (int g = 0; g < Gg; g++) {
        mm_gemm<<<dim3(16, 100), 256>>>(x, Hh, gat_W + (size_t)g * Hh * HPH,
                                        HPH, HPH, nullptr, xp, HPH, ROWS, Hh, 0);
        gat_coef<<<ROWS, 256>>>(xp, gat_asrc_w, gat_adst_w, asrc, adst, g);
        gat_softmax<<<dim3(Nn, Bb), 256>>>(asrc, adst, adj, attn);
        mm_msg_gemm<<<dim3(2, 2, 512), 256>>>(attn, xp, msgh);
        gat_msg_reduce<<<ROWS, Hh>>>(msgh, gat_bias, g, x);
    }
    add_ln<<<ROWS, Hh>>>(enc, x, emb, gat_ln, 1);

    // ---- Transformer encoder ----
    for (int l = 0; l < Ll; l++) {
        const float* W = attn_W + (size_t)l * 4 * Hh * Hh;
        const float* bq = attn_b + (size_t)l * 4 * Hh;
        // fused QKV: N=768, B = 3 consecutive [256,256] matrices
        mm_gemm<<<dim3(6, 100), 256>>>(emb, Hh, W, Hh, Hh, bq, qkv, 768, ROWS, Hh, 1);
        mha_attn<<<dim3(NHh, Bb), 256, 84000>>>(qkv, adj, ctx);
        mm_gemm<<<dim3(2, 100), 256>>>(ctx, Hh, W + 3 * Hh * Hh, Hh, Hh,
                                       bq + 3 * Hh, tmp, Hh, ROWS, Hh, 1);
        add_ln<<<ROWS, Hh>>>(emb, tmp, emb, ln1 + (size_t)l * 2 * Hh, 0);
        mm_gemm<<<dim3(4, 100), 256>>>(emb, Hh, ffn_W1 + (size_t)l * Hh * Ff, Ff, Ff,
                                       ffn_b1 + (size_t)l * Ff, t1, Ff, ROWS, Hh, 3);
        mm_gemm<<<dim3(2, 100), 256>>>(t1, Ff, ffn_W2 + (size_t)l * Ff * Hh, Hh, Hh,
                                       ffn_b2 + (size_t)l * Hh, tmp, Hh, ROWS, Ff, 1);
        add_ln<<<ROWS, Hh>>>(emb, tmp, emb, ln2 + (size_t)l * 2 * Hh, 0);
    }

    // ---- LSTM cell + pointer head ----
    lstm_kernel<<<Bb, Hh>>>(dec_input, dec_h, dec_c, lstm_Wih, lstm_Whh, lstm_b, gh, gc, out);
    mm_gemm<<<dim3(2, 100), 256>>>(emb, Hh, ptr_Wref, Hh, Hh, nullptr, refb, Hh, ROWS, Hh, 0);
    mm_gemm<<<dim3(2, 1), 256>>>(gh, Hh, ptr_Wq, Hh, Hh, nullptr, qh, Hh, Bb, Hh, 0);
    ptr_kernel<<<Bb, 256>>>(refb, qh, ptr_v, mask, out);

    // ---- emit emb ----
    copy_kernel<<<12800, 256>>>(emb, out + OUT_EMB);
}

// round 9
// speedup vs baseline: 1.9487x; 1.1972x over previous
#include <cuda_runtime.h>
#include <cuda_fp16.h>
#include <math.h>
#include <stdint.h>

#define Bb 64
#define Nn 200
#define Hh 256
#define NHh 8
#define Gg 2
#define Ll 3
#define Ff 512
#define ROWS 12800
#define HPH 2048

// ---- output layout (floats) ----
#define OUT_POLICY 0
#define OUT_H      12800
#define OUT_C      29184
#define OUT_EMB    45568

// ---- scratch arena offsets (floats) ----
#define OFF_X    0
#define OFF_XP   3276800
#define OFF_ASRC 29491200
#define OFF_ADST 29593600
#define OFF_ATTN 29696000
#define OFF_MSGH 50176000
#define OFF_EMB  76390400
#define OFF_QKV  79667200           // [12800, 768]
#define OFF_CTX  89497600
#define OFF_T1   92774400
#define OFF_TMP  99328000
#define OFF_REF  102604800
#define OFF_HB   105881600
#define OFF_CB   105897984
#define OFF_QH   105914368
#define SCRATCH_TOTAL 105930752

__device__ float g_scratch[SCRATCH_TOTAL];

__device__ __forceinline__ float warp_sum(float v) {
#pragma unroll
    for (int o = 16; o > 0; o >>= 1) v += __shfl_xor_sync(0xffffffffu, v, o);
    return v;
}
__device__ __forceinline__ float warp_max(float v) {
#pragma unroll
    for (int o = 16; o > 0; o >>= 1) v = fmaxf(v, __shfl_xor_sync(0xffffffffu, v, o));
    return v;
}
__device__ __forceinline__ float sigmf(float x) { return 1.f / (1.f + __expf(-x)); }

__device__ __forceinline__ uint32_t pack2(float lo, float hi) {
    __half2 h = __floats2half2_rn(lo, hi);
    return *(uint32_t*)&h;
}

// mma.sync m16n8k16 fp16->fp32 (baseline sm_80+ — valid on compute_103)
__device__ __forceinline__ void mma16(float* c, const uint32_t* a, const uint32_t* b) {
    asm volatile(
        "mma.sync.aligned.m16n8k16.row.col.f32.f16.f16.f32 "
        "{%0,%1,%2,%3}, {%4,%5,%6,%7}, {%8,%9}, {%0,%1,%2,%3};"
        : "+f"(c[0]), "+f"(c[1]), "+f"(c[2]), "+f"(c[3])
        : "r"(a[0]), "r"(a[1]), "r"(a[2]), "r"(a[3]), "r"(b[0]), "r"(b[1]));
}

// ============================================================================
// fp16 mma.sync GEMM core.  C tile [128,128] = A[row0:+128, :K] @ B[:K, n-tile]
// A: K-major fp32 (lda); zero-fill rows>=M, k>=K (K%4==0 — holds: 200/256/512).
// Bp: pre-offset to tile col base, [K, >=128] with stride ldb (K even).
// Smem holds packed half2 along K: As/Bs are uint32[k2][row|col], k2 = k/2.
// K-chunk = 32 k (16 half2 rows). Fragment index pattern identical to the
// validated tf32 version, with the k-dim in half2 units.
// flags: 1=bias, 2=relu.
// ============================================================================
#define PAD 132

__device__ __forceinline__ void mm_core(
    const float* __restrict__ A, int lda, int row0, int M, int K,
    const float* __restrict__ Bp, int ldb,
    const float* __restrict__ biasp, float* __restrict__ Cp, int ldc, int flags)
{
    __shared__ uint32_t As[2][16][PAD];
    __shared__ uint32_t Bs[2][16][PAD];
    int tid = threadIdx.x, lane = tid & 31, wid = tid >> 5;
    int wy = wid & 3, wx = wid >> 2;
    int g = lane >> 2, tg = lane & 3;

    const int T = (K + 31) >> 5;
    const float4 z4 = make_float4(0.f, 0.f, 0.f, 0.f);

    float c[2][8][4];
#pragma unroll
    for (int ma = 0; ma < 2; ma++)
#pragma unroll
        for (int na = 0; na < 8; na++)
#pragma unroll
            for (int q = 0; q < 4; q++) c[ma][na][q] = 0.f;

    // A: 4 float4 loads/thread (128 rows x 32 k). B: 2 k-row pairs/thread.
    int a_row[4], a_kc[4], b_k2[2], b_nb[2];
#pragma unroll
    for (int i = 0; i < 4; i++) {
        int idx = tid + i * 256;
        a_row[i] = idx >> 3;            // 0..127
        a_kc[i] = (idx & 7) * 4;        // 0,4,..,28
    }
#pragma unroll
    for (int i = 0; i < 2; i++) {
        int idx = tid + i * 256;
        b_k2[i] = idx >> 5;             // 0..15 (half2 row)
        b_nb[i] = (idx & 31) * 4;       // 0..124
    }

    float4 ra[4], rb0[2], rb1[2];

#define LOADG(t)                                                                     \
    {                                                                                \
        int k0 = (t) * 32;                                                           \
        _Pragma("unroll")                                                            \
        for (int i = 0; i < 4; i++) {                                                \
            ra[i] = (row0 + a_row[i] < M && k0 + a_kc[i] < K)                        \
                ? *(const float4*)&A[(size_t)(row0 + a_row[i]) * lda + k0 + a_kc[i]] \
                : z4;                                                                \
        }                                                                            \
        _Pragma("unroll")                                                            \
        for (int i = 0; i < 2; i++) {                                                \
            int kk = k0 + 2 * b_k2[i];                                               \
            if (kk < K) {                                                            \
                rb0[i] = *(const float4*)&Bp[(size_t)kk * ldb + b_nb[i]];            \
                rb1[i] = *(const float4*)&Bp[(size_t)(kk + 1) * ldb + b_nb[i]];      \
            } else { rb0[i] = z4; rb1[i] = z4; }                                     \
        }                                                                            \
    }
#define STS(s)                                                                       \
    {                                                                                \
        _Pragma("unroll")                                                            \
        for (int i = 0; i < 4; i++) {                                                \
            int k2 = a_kc[i] >> 1;                                                   \
            As[s][k2 + 0][a_row[i]] = pack2(ra[i].x, ra[i].y);                       \
            As[s][k2 + 1][a_row[i]] = pack2(ra[i].z, ra[i].w);                       \
        }                                                                            \
        _Pragma("unroll")                                                            \
        for (int i = 0; i < 2; i++) {                                                \
            uint4 p;                                                                 \
            p.x = pack2(rb0[i].x, rb1[i].x);                                         \
            p.y = pack2(rb0[i].y, rb1[i].y);                                         \
            p.z = pack2(rb0[i].z, rb1[i].z);                                         \
            p.w = pack2(rb0[i].w, rb1[i].w);                                         \
            *(uint4*)&Bs[s][b_k2[i]][b_nb[i]] = p;                                   \
        }                                                                            \
    }

    LOADG(0)
    STS(0)
    __syncthreads();

    for (int t = 0; t < T; t++) {
        int s = t & 1;
        if (t + 1 < T) LOADG(t + 1)

#pragma unroll
        for (int ks = 0; ks < 2; ks++) {
            int kb = ks * 8;                     // half2-row base (16 k per step)
            uint32_t afr[2][4], bfr[8][2];
#pragma unroll
            for (int ma = 0; ma < 2; ma++) {
                int r = wy * 32 + ma * 16 + g;
                afr[ma][0] = As[s][kb + tg][r];
                afr[ma][1] = As[s][kb + tg][r + 8];
                afr[ma][2] = As[s][kb + tg + 4][r];
                afr[ma][3] = As[s][kb + tg + 4][r + 8];
            }
#pragma unroll
            for (int na = 0; na < 8; na++) {
                int col = wx * 64 + na * 8 + g;
                bfr[na][0] = Bs[s][kb + tg][col];
                bfr[na][1] = Bs[s][kb + tg + 4][col];
            }
#pragma unroll
            for (int ma = 0; ma < 2; ma++)
#pragma unroll
                for (int na = 0; na < 8; na++) mma16(c[ma][na], afr[ma], bfr[na]);
        }

        if (t + 1 < T) STS(s ^ 1)
        __syncthreads();
    }

    // epilogue
#pragma unroll
    for (int ma = 0; ma < 2; ma++) {
        int r = row0 + wy * 32 + ma * 16 + g;
#pragma unroll
        for (int na = 0; na < 8; na++) {
            int colb = wx * 64 + na * 8 + tg * 2;
            float b0 = 0.f, b1 = 0.f;
            if (flags & 1) { b0 = biasp[colb]; b1 = biasp[colb + 1]; }
            float v0 = c[ma][na][0] + b0, v1 = c[ma][na][1] + b1;
            float v2 = c[ma][na][2] + b0, v3 = c[ma][na][3] + b1;
            if (flags & 2) {
                v0 = fmaxf(v0, 0.f); v1 = fmaxf(v1, 0.f);
                v2 = fmaxf(v2, 0.f); v3 = fmaxf(v3, 0.f);
            }
            if (r < M)     *(float2*)&Cp[(size_t)r * ldc + colb]       = make_float2(v0, v1);
            if (r + 8 < M) *(float2*)&Cp[(size_t)(r + 8) * ldc + colb] = make_float2(v2, v3);
        }
    }
#undef LOADG
#undef STS
}

// Regular GEMM: B may be a sequence of [K, bsplit] matrices (bsplit == ldb).
__global__ void __launch_bounds__(256)
mm_gemm(const float* __restrict__ A, int lda, const float* __restrict__ B, int ldb,
        int bsplit, const float* __restrict__ bias, float* __restrict__ C, int ldc,
        int M, int K, int flags) {
    int n0 = blockIdx.x * 128;
    int row0 = blockIdx.y * 128;
    const float* Bp = B + (size_t)(n0 / bsplit) * K * bsplit + (n0 % bsplit);
    mm_core(A, lda, row0, M, K, Bp, ldb,
            (flags & 1) ? bias + n0 : nullptr, C + n0, ldc, flags);
}

// GAT message GEMM: per (b,h): msg[j, d] = sum_i attn[b,h,j,i] * xp[b, i, h*256+d]
__global__ void __launch_bounds__(256)
mm_msg_gemm(const float* __restrict__ attn, const float* __restrict__ xp,
            float* __restrict__ msgh) {
    int z = blockIdx.z;
    int b = z >> 3, h = z & 7;
    int n0 = blockIdx.x * 128;
    int row0 = blockIdx.y * 128;
    const float* A = attn + (size_t)z * Nn * Nn;
    const float* Bp = xp + (size_t)b * Nn * HPH + h * Hh + n0;
    float* Cp = msgh + (size_t)b * Nn * HPH + h * Hh + n0;
    mm_core(A, Nn, row0, Nn, Nn, Bp, HPH, nullptr, Cp, HPH, 0);
}

// ============================================================================
// GAT coefficient / softmax / reduce
// ============================================================================
__global__ void gat_coef(const float* __restrict__ xp, const float* __restrict__ att_src,
                         const float* __restrict__ att_dst, float* __restrict__ asrc,
                         float* __restrict__ adst, int g) {
    int row = blockIdx.x;
    int b = row / Nn, n = row % Nn;
    int h = threadIdx.x >> 5, lane = threadIdx.x & 31;
    const float* xr = xp + (size_t)row * HPH + h * Hh;
    const float* as = att_src + (size_t)(g * NHh + h) * Hh;
    const float* ad = att_dst + (size_t)(g * NHh + h) * Hh;
    float s1 = 0.f, s2 = 0.f;
    for (int d = lane; d < Hh; d += 32) {
        float xv = xr[d];
        s1 += xv * as[d];
        s2 += xv * ad[d];
    }
    s1 = warp_sum(s1);
    s2 = warp_sum(s2);
    if (!lane) {
        asrc[(b * NHh + h) * Nn + n] = s1;
        adst[(b * NHh + h) * Nn + n] = s2;
    }
}

__global__ void gat_softmax(const float* __restrict__ asrc, const float* __restrict__ adst,
                            const int* __restrict__ adj, float* __restrict__ attn) {
    int j = blockIdx.x, b = blockIdx.y;
    __shared__ float am[Nn];
    __shared__ float Ps[NHh][Nn];
    int tid = threadIdx.x;
    if (tid < Nn)
        am[tid] = (tid == j || adj[(b * Nn + tid) * Nn + j] > 0) ? 1.f : 0.f;
    __syncthreads();
    int h = tid >> 5, lane = tid & 31;
    float ad = adst[(b * NHh + h) * Nn + j];
    const float* as = asrc + (b * NHh + h) * Nn;
    float* arow = attn + (size_t)((b * NHh + h) * Nn + j) * Nn;
    float m = -1e30f;
    for (int i = lane; i < Nn; i += 32) {
        float e = ad + as[i];
        e = e > 0.f ? e : 0.2f * e;        // leaky_relu(0.2)
        e = am[i] > 0.f ? e : -1e9f;
        Ps[h][i] = e;
        m = fmaxf(m, e);
    }
    m = warp_max(m);
    float s = 0.f;
    for (int i = lane; i < Nn; i += 32) {
        float e = __expf(Ps[h][i] - m);
        Ps[h][i] = e;
        s += e;
    }
    s = warp_sum(s);
    float inv = 1.f / s;
    for (int i = lane; i < Nn; i += 32) arow[i] = Ps[h][i] * inv;
}

__global__ void gat_msg_reduce(const float* __restrict__ msgh, const float* __restrict__ gbias,
                               int g, float* __restrict__ x) {
    int row = blockIdx.x, d = threadIdx.x;
    const float* mr = msgh + (size_t)row * HPH;
    float s = 0.f;
#pragma unroll
    for (int h = 0; h < NHh; h++) s += mr[h * Hh + d];
    s = s * (1.f / NHh) + gbias[g * Hh + d];
    x[row * Hh + d] += fmaxf(s, 0.f);
}

// ============================================================================
// add + LayerNorm
// ============================================================================
__global__ void add_ln(const float* __restrict__ a, const float* __restrict__ bsrc,
                       float* __restrict__ outp, const float* __restrict__ sb, int relu_b) {
    int row = blockIdx.x, d = threadIdx.x;
    float bv = bsrc[(size_t)row * Hh + d];
    if (relu_b) bv = fmaxf(bv, 0.f);
    float v = a[(size_t)row * Hh + d] + bv;
    __shared__ float sw[8], sw2[8];
    float s = warp_sum(v), s2 = warp_sum(v * v);
    int w = d >> 5, lane = d & 31;
    if (!lane) { sw[w] = s; sw2[w] = s2; }
    __syncthreads();
    float ts = 0.f, ts2 = 0.f;
#pragma unroll
    for (int i = 0; i < 8; i++) { ts += sw[i]; ts2 += sw2[i]; }
    float mean = ts * (1.f / Hh);
    float var = ts2 * (1.f / Hh) - mean * mean;
    outp[(size_t)row * Hh + d] = (v - mean) * rsqrtf(var + 1e-5f) * sb[d] + sb[Hh + d];
}

// ============================================================================
// Fused masked MHA (reads fused qkv buffer [rows, 768])
// ============================================================================
__global__ void mha_attn(const float* __restrict__ qkv, const int* __restrict__ adj,
                         float* __restrict__ ctx) {
    int h = blockIdx.x, b = blockIdx.y;
    extern __shared__ float sm[];
    float* Qs = sm;
    float* Ks = Qs + Nn * 32;
    float* Vs = Ks + Nn * 33;
    float* Ps = Vs + Nn * 32;
    int tid = threadIdx.x;
    for (int idx = tid; idx < Nn * 32; idx += 256) {
        int i = idx >> 5, d = idx & 31;
        int gi = (b * Nn + i) * 768 + h * 32 + d;
        Qs[i * 32 + d] = qkv[gi];
        Ks[i * 33 + d] = qkv[gi + 256];
        Vs[i * 32 + d] = qkv[gi + 512];
    }
    __syncthreads();
    int w = tid >> 5, lane = tid & 31;
    float* P = Ps + w * Nn;
    const float scale = 0.17677669529663687f;   // 1/sqrt(32)
    for (int j = w; j < Nn; j += 8) {
        const float* qj = Qs + j * 32;
        const int* arow = adj + (b * Nn + j) * Nn;
        float m = -1e30f;
        for (int i = lane; i < Nn; i += 32) {
            const float* kr = Ks + i * 33;
            float s = 0.f;
#pragma unroll
            for (int d = 0; d < 32; d++) s += qj[d] * kr[d];
            s = arow[i] > 0 ? s * scale : -1e9f;
            P[i] = s;
            m = fmaxf(m, s);
        }
        m = warp_max(m);
        float sum = 0.f;
        for (int i = lane; i < Nn; i += 32) {
            float e = __expf(P[i] - m);
            P[i] = e;
            sum += e;
        }
        sum = warp_sum(sum);
        float inv = 1.f / sum;
        __syncwarp();
        float acc = 0.f;
        for (int i = 0; i < Nn; i++) acc += P[i] * Vs[i * 32 + lane];
        ctx[(b * Nn + j) * Hh + h * 32 + lane] = acc * inv;
        __syncwarp();
    }
}

// ============================================================================
// LSTM cell
// ============================================================================
__global__ void lstm_kernel(const float* __restrict__ xin, const float* __restrict__ hin,
                            const float* __restrict__ cin, const float* __restrict__ Wih,
                            const float* __restrict__ Whh, const float* __restrict__ bias,
                            float* __restrict__ gh, float* __restrict__ gc,
                            float* __restrict__ out) {
    int b = blockIdx.x, tid = threadIdx.x;
    __shared__ float xs[Hh], hs[Hh], gsh[4 * Hh];
    xs[tid] = xin[b * Hh + tid];
    hs[tid] = hin[b * Hh + tid];
    __syncthreads();
    for (int r = tid; r < 4 * Hh; r += Hh) {
        const float* wi = Wih + (size_t)r * Hh;
        const float* wh = Whh + (size_t)r * Hh;
        float s = bias[r];
        for (int d = 0; d < Hh; d++) s += xs[d] * wi[d] + hs[d] * wh[d];
        gsh[r] = s;
    }
    __syncthreads();
    float ig = gsh[tid], fg = gsh[Hh + tid], gg = gsh[2 * Hh + tid], og = gsh[3 * Hh + tid];
    float c = sigmf(fg) * cin[b * Hh + tid] + sigmf(ig) * tanhf(gg);
    float hv = sigmf(og) * tanhf(c);
    gh[b * Hh + tid] = hv;
    gc[b * Hh + tid] = c;
    out[OUT_H + b * Hh + tid] = hv;
    out[OUT_C + b * Hh + tid] = c;
}

// ============================================================================
// Pointer head
// ============================================================================
__global__ void ptr_kernel(const float* __restrict__ refb, const float* __restrict__ qh,
                           const float* __restrict__ vvec, const int* __restrict__ mask,
                           float* __restrict__ out) {
    int b = blockIdx.x, tid = threadIdx.x;
    __shared__ float us[Nn];
    __shared__ float red[8];
    int w = tid >> 5, lane = tid & 31;
    const float* qv = qh + b * Hh;
    for (int n = w; n < Nn; n += 8) {
        const float* r = refb + (size_t)(b * Nn + n) * Hh;
        float s = 0.f;
        for (int d = lane; d < Hh; d += 32) s += tanhf(r[d] + qv[d]) * vvec[d];
        s = warp_sum(s);
        if (!lane) us[n] = s;
    }
    __syncthreads();
    float vvv = -1e30f;
    if (tid < Nn) vvv = mask[b * Nn + tid] > 0 ? us[tid] : -1e9f;
    float m = warp_max(vvv);
    if (!lane) red[w] = m;
    __syncthreads();
    float bm = red[0];
#pragma unroll
    for (int i = 1; i < 8; i++) bm = fmaxf(bm, red[i]);
    float e = (tid < Nn) ? __expf(vvv - bm) : 0.f;
    float s = warp_sum(e);
    __syncthreads();
    if (!lane) red[w] = s;
    __syncthreads();
    float bs = 0.f;
#pragma unroll
    for (int i = 0; i < 8; i++) bs += red[i];
    if (tid < Nn) out[OUT_POLICY + b * Nn + tid] = e / bs;
}

__global__ void copy_kernel(const float* __restrict__ src, float* __restrict__ dst) {
    int i = blockIdx.x * 256 + threadIdx.x;
    dst[i] = src[i];
}

// ============================================================================
// Launch
// ============================================================================
extern "C" void kernel_launch(void* const* d_in, const int* in_sizes, int n_in,
                              void* d_out, int out_size) {
    const float* enc        = (const float*)d_in[0];
    const float* dec_input  = (const float*)d_in[1];
    const float* dec_h      = (const float*)d_in[2];
    const float* dec_c      = (const float*)d_in[3];
    const float* gat_W      = (const float*)d_in[4];
    const float* gat_asrc_w = (const float*)d_in[5];
    const float* gat_adst_w = (const float*)d_in[6];
    const float* gat_bias   = (const float*)d_in[7];
    const float* gat_ln     = (const float*)d_in[8];
    const float* attn_W     = (const float*)d_in[9];
    const float* attn_b     = (const float*)d_in[10];
    const float* ln1        = (const float*)d_in[11];
    const float* ffn_W1     = (const float*)d_in[12];
    const float* ffn_b1     = (const float*)d_in[13];
    const float* ffn_W2     = (const float*)d_in[14];
    const float* ffn_b2     = (const float*)d_in[15];
    const float* ln2        = (const float*)d_in[16];
    const float* lstm_Wih   = (const float*)d_in[17];
    const float* lstm_Whh   = (const float*)d_in[18];
    const float* lstm_b     = (const float*)d_in[19];
    const float* ptr_Wref   = (const float*)d_in[20];
    const float* ptr_Wq     = (const float*)d_in[21];
    const float* ptr_v      = (const float*)d_in[22];
    const int*   adj        = (const int*)d_in[23];
    const int*   mask       = (const int*)d_in[24];
    float* out = (float*)d_out;

    float* S = nullptr;
    cudaGetSymbolAddress((void**)&S, g_scratch);
    float* x    = S + OFF_X;
    float* xp   = S + OFF_XP;
    float* asrc = S + OFF_ASRC;
    float* adst = S + OFF_ADST;
    float* attn = S + OFF_ATTN;
    float* msgh = S + OFF_MSGH;
    float* emb  = S + OFF_EMB;
    float* qkv  = S + OFF_QKV;
    float* ctx  = S + OFF_CTX;
    float* t1   = S + OFF_T1;
    float* tmp  = S + OFF_TMP;
    float* refb = S + OFF_REF;
    float* gh   = S + OFF_HB;
    float* gc   = S + OFF_CB;
    float* qh   = S + OFF_QH;

    cudaFuncSetAttribute(mha_attn, cudaFuncAttributeMaxDynamicSharedMemorySize, 84000);

    // x = enc_inputs
    copy_kernel<<<12800, 256>>>(enc, x);

    // ---- GAT stack ----
    for (int g = 0; g < Gg; g++) {
        mm_gemm<<<dim3(16, 100), 256>>>(x, Hh, gat_W + (size_t)g * Hh * HPH,
                                        HPH, HPH, nullptr, xp, HPH, ROWS, Hh, 0);
        gat_coef<<<ROWS, 256>>>(xp, gat_asrc_w, gat_adst_w, asrc, adst, g);
        gat_softmax<<<dim3(Nn, Bb), 256>>>(asrc, adst, adj, attn);
        mm_msg_gemm<<<dim3(2, 2, 512), 256>>>(attn, xp, msgh);
        gat_msg_reduce<<<ROWS, Hh>>>(msgh, gat_bias, g, x);
    }
    add_ln<<<ROWS, Hh>>>(enc, x, emb, gat_ln, 1);

    // ---- Transformer encoder ----
    for (int l = 0; l < Ll; l++) {
        const float* W = attn_W + (size_t)l * 4 * Hh * Hh;
        const float* bq = attn_b + (size_t)l * 4 * Hh;
        // fused QKV: N=768, B = 3 consecutive [256,256] matrices
        mm_gemm<<<dim3(6, 100), 256>>>(emb, Hh, W, Hh, Hh, bq, qkv, 768, ROWS, Hh, 1);
        mha_attn<<<dim3(NHh, Bb), 256, 84000>>>(qkv, adj, ctx);
        mm_gemm<<<dim3(2, 100), 256>>>(ctx, Hh, W + 3 * Hh * Hh, Hh, Hh,
                                       bq + 3 * Hh, tmp, Hh, ROWS, Hh, 1);
        add_ln<<<ROWS, Hh>>>(emb, tmp, emb, ln1 + (size_t)l * 2 * Hh, 0);
        mm_gemm<<<dim3(4, 100), 256>>>(emb, Hh, ffn_W1 + (size_t)l * Hh * Ff, Ff, Ff,
                                       ffn_b1 + (size_t)l * Ff, t1, Ff, ROWS, Hh, 3);
        mm_gemm<<<dim3(2, 100), 256>>>(t1, Ff, ffn_W2 + (size_t)l * Ff * Hh, Hh, Hh,
                                       ffn_b2 + (size_t)l * Hh, tmp, Hh, ROWS, Ff, 1);
        add_ln<<<ROWS, Hh>>>(emb, tmp, emb, ln2 + (size_t)l * 2 * Hh, 0);
    }

    // ---- LSTM cell + pointer head ----
    lstm_kernel<<<Bb, Hh>>>(dec_input, dec_h, dec_c, lstm_Wih, lstm_Whh, lstm_b, gh, gc, out);
    mm_gemm<<<dim3(2, 100), 256>>>(emb, Hh, ptr_Wref, Hh, Hh, nullptr, refb, Hh, ROWS, Hh, 0);
    mm_gemm<<<dim3(2, 1), 256>>>(gh, Hh, ptr_Wq, Hh, Hh, nullptr, qh, Hh, Bb, Hh, 0);
    ptr_kernel<<<Bb, 256>>>(refb, qh, ptr_v, mask, out);

    // ---- emit emb ----
    copy_kernel<<<12800, 256>>>(emb, out + OUT_EMB);
}

// round 10
// speedup vs baseline: 2.0655x; 1.0599x over previous
#include <cuda_runtime.h>
#include <cuda_fp16.h>
#include <math.h>
#include <stdint.h>

#define Bb 64
#define Nn 200
#define Hh 256
#define NHh 8
#define Gg 2
#define Ll 3
#define Ff 512
#define ROWS 12800
#define HPH 2048

// ---- output layout (floats) ----
#define OUT_POLICY 0
#define OUT_H      12800
#define OUT_C      29184
#define OUT_EMB    45568

// ---- fp32 scratch arena offsets (floats) ----
#define OFF_X    0
#define OFF_ASRC 3276800
#define OFF_ADST 3379200
#define OFF_EMB  3481600
#define OFF_QKV  6758400            // [12800, 768]
#define OFF_TMP  16588800
#define OFF_REF  19865600
#define OFF_HB   23142400
#define OFF_CB   23158784
#define OFF_QH   23175168
#define SCRATCH_TOTAL 23191552

__device__ float g_scratch[SCRATCH_TOTAL];

// ---- half scratch arena offsets (halves) ----
#define HS_XPH   0                   // [12800, 2048]
#define HS_ATTNH 26214400            // [512, 200, 200]
#define HS_MSGH  46694400            // [12800, 2048]
#define HS_XH    72908800            // [12800, 256]
#define HS_EMBH  76185600            // [12800, 256]
#define HS_CTXH  79462400            // [12800, 256]
#define HS_T1H   82739200            // [12800, 512]
#define HW_GAT   89292800            // 2 x [256, 2048]
#define HW_ATTN  90341376            // 3 x 4 x [256, 256]
#define HW_FFN1  91127808            // 3 x [256, 512]
#define HW_FFN2  91521024            // 3 x [512, 256]
#define HW_PREF  91914240            // [256, 256]
#define HW_PQ    91979776            // [256, 256]
#define HSCRATCH_TOTAL 92045312

__device__ __half g_hscratch[HSCRATCH_TOTAL];

__device__ __forceinline__ float warp_sum(float v) {
#pragma unroll
    for (int o = 16; o > 0; o >>= 1) v += __shfl_xor_sync(0xffffffffu, v, o);
    return v;
}
__device__ __forceinline__ float warp_max(float v) {
#pragma unroll
    for (int o = 16; o > 0; o >>= 1) v = fmaxf(v, __shfl_xor_sync(0xffffffffu, v, o));
    return v;
}
__device__ __forceinline__ float sigmf(float x) { return 1.f / (1.f + __expf(-x)); }

__device__ __forceinline__ uint32_t pack2(float lo, float hi) {
    __half2 h = __floats2half2_rn(lo, hi);
    return *(uint32_t*)&h;
}
__device__ __forceinline__ uint32_t prmtb(uint32_t a, uint32_t b, uint32_t sel) {
    uint32_t r;
    asm("prmt.b32 %0, %1, %2, %3;" : "=r"(r) : "r"(a), "r"(b), "r"(sel));
    return r;
}

// mma.sync m16n8k16 fp16->fp32 (baseline sm_80+ — valid on compute_103)
__device__ __forceinline__ void mma16(float* c, const uint32_t* a, const uint32_t* b) {
    asm volatile(
        "mma.sync.aligned.m16n8k16.row.col.f32.f16.f16.f32 "
        "{%0,%1,%2,%3}, {%4,%5,%6,%7}, {%8,%9}, {%0,%1,%2,%3};"
        : "+f"(c[0]), "+f"(c[1]), "+f"(c[2]), "+f"(c[3])
        : "r"(a[0]), "r"(a[1]), "r"(a[2]), "r"(a[3]), "r"(b[0]), "r"(b[1]));
}

// ============================================================================
// fp16 mma.sync GEMM core.  C tile [128,128] = A[row0:+128, :K] @ B[:K, n-tile]
// AH: A is __half (K-major, 16B-aligned rows, K%8==0) else fp32 (K%4==0).
// B: always __half, [K, >=128] stride ldb, pre-offset to tile col base.
// CH: C written as __half else fp32. flags: 1=bias(fp32), 2=relu.
// Smem: packed half2 along K: As/Bs uint32[k2][row|col]. K-chunk = 32.
// ============================================================================
#define PAD 132

template<int AH, int CH>
__device__ __forceinline__ void mm_core(
    const void* __restrict__ Avp, int lda, int row0, int M, int K,
    const __half* __restrict__ Bp, int ldb,
    const float* __restrict__ biasp, void* __restrict__ Cvp, int ldc, int flags)
{
    __shared__ uint32_t As[2][16][PAD];
    __shared__ uint32_t Bs[2][16][PAD];
    const float* Af = (const float*)Avp;
    const __half* Ah = (const __half*)Avp;
    int tid = threadIdx.x, lane = tid & 31, wid = tid >> 5;
    int wy = wid & 3, wx = wid >> 2;
    int g = lane >> 2, tg = lane & 3;

    const int T = (K + 31) >> 5;
    const float4 z4 = make_float4(0.f, 0.f, 0.f, 0.f);
    const uint4 zu4 = make_uint4(0u, 0u, 0u, 0u);

    float c[2][8][4];
#pragma unroll
    for (int ma = 0; ma < 2; ma++)
#pragma unroll
        for (int na = 0; na < 8; na++)
#pragma unroll
            for (int q = 0; q < 4; q++) c[ma][na][q] = 0.f;

    // A fp32 mapping: 4 float4/thread.  A half mapping: 2 uint4/thread.
    int af_row[4], af_kc[4];
#pragma unroll
    for (int i = 0; i < 4; i++) {
        int idx = tid + i * 256;
        af_row[i] = idx >> 3;
        af_kc[i] = (idx & 7) * 4;
    }
    int ah_row[2], ah_k8[2];
#pragma unroll
    for (int i = 0; i < 2; i++) {
        int idx = tid + i * 256;
        ah_row[i] = idx >> 2;           // 0..127
        ah_k8[i] = (idx & 3) * 8;       // 0,8,16,24
    }
    // B mapping: 1 pass, 16 k2-rows x 16 col-groups of 8.
    int b_k2 = tid >> 4;                // 0..15
    int b_nb = (tid & 15) * 8;          // 0..120

    float4 raf[4];
    uint4 rah[2], rb0, rb1;

#define LOADG(t)                                                                      \
    {                                                                                 \
        int k0 = (t) * 32;                                                            \
        if (AH) {                                                                     \
            _Pragma("unroll")                                                         \
            for (int i = 0; i < 2; i++)                                               \
                rah[i] = (row0 + ah_row[i] < M && k0 + ah_k8[i] < K)                  \
                    ? *(const uint4*)&Ah[(size_t)(row0 + ah_row[i]) * lda + k0 + ah_k8[i]] \
                    : zu4;                                                            \
        } else {                                                                      \
            _Pragma("unroll")                                                         \
            for (int i = 0; i < 4; i++)                                               \
                raf[i] = (row0 + af_row[i] < M && k0 + af_kc[i] < K)                  \
                    ? *(const float4*)&Af[(size_t)(row0 + af_row[i]) * lda + k0 + af_kc[i]] \
                    : z4;                                                             \
        }                                                                             \
        int kk = k0 + 2 * b_k2;                                                       \
        if (kk < K) {                                                                 \
            rb0 = *(const uint4*)&Bp[(size_t)kk * ldb + b_nb];                        \
            rb1 = *(const uint4*)&Bp[(size_t)(kk + 1) * ldb + b_nb];                  \
        } else { rb0 = zu4; rb1 = zu4; }                                              \
    }
#define STS(s)                                                                        \
    {                                                                                 \
        if (AH) {                                                                     \
            _Pragma("unroll")                                                         \
            for (int i = 0; i < 2; i++) {                                             \
                int k2 = ah_k8[i] >> 1;                                               \
                As[s][k2 + 0][ah_row[i]] = rah[i].x;                                  \
                As[s][k2 + 1][ah_row[i]] = rah[i].y;                                  \
                As[s][k2 + 2][ah_row[i]] = rah[i].z;                                  \
                As[s][k2 + 3][ah_row[i]] = rah[i].w;                                  \
            }                                                                         \
        } else {                                                                      \
            _Pragma("unroll")                                                         \
            for (int i = 0; i < 4; i++) {                                             \
                int k2 = af_kc[i] >> 1;                                               \
                As[s][k2 + 0][af_row[i]] = pack2(raf[i].x, raf[i].y);                 \
                As[s][k2 + 1][af_row[i]] = pack2(raf[i].z, raf[i].w);                 \
            }                                                                         \
        }                                                                             \
        uint4 p0, p1;                                                                 \
        p0.x = prmtb(rb0.x, rb1.x, 0x5410); p0.y = prmtb(rb0.x, rb1.x, 0x7632);       \
        p0.z = prmtb(rb0.y, rb1.y, 0x5410); p0.w = prmtb(rb0.y, rb1.y, 0x7632);       \
        p1.x = prmtb(rb0.z, rb1.z, 0x5410); p1.y = prmtb(rb0.z, rb1.z, 0x7632);       \
        p1.z = prmtb(rb0.w, rb1.w, 0x5410); p1.w = prmtb(rb0.w, rb1.w, 0x7632);       \
        *(uint4*)&Bs[s][b_k2][b_nb + 0] = p0;                                         \
        *(uint4*)&Bs[s][b_k2][b_nb + 4] = p1;                                         \
    }

    LOADG(0)
    STS(0)
    __syncthreads();

    for (int t = 0; t < T; t++) {
        int s = t & 1;
        if (t + 1 < T) LOADG(t + 1)

#pragma unroll
        for (int ks = 0; ks < 2; ks++) {
            int kb = ks * 8;
            uint32_t afr[2][4], bfr[8][2];
#pragma unroll
            for (int ma = 0; ma < 2; ma++) {
                int r = wy * 32 + ma * 16 + g;
                afr[ma][0] = As[s][kb + tg][r];
                afr[ma][1] = As[s][kb + tg][r + 8];
                afr[ma][2] = As[s][kb + tg + 4][r];
                afr[ma][3] = As[s][kb + tg + 4][r + 8];
            }
#pragma unroll
            for (int na = 0; na < 8; na++) {
                int col = wx * 64 + na * 8 + g;
                bfr[na][0] = Bs[s][kb + tg][col];
                bfr[na][1] = Bs[s][kb + tg + 4][col];
            }
#pragma unroll
            for (int ma = 0; ma < 2; ma++)
#pragma unroll
                for (int na = 0; na < 8; na++) mma16(c[ma][na], afr[ma], bfr[na]);
        }

        if (t + 1 < T) STS(s ^ 1)
        __syncthreads();
    }

    // epilogue
    float* Cf = (float*)Cvp;
    __half* Chh = (__half*)Cvp;
#pragma unroll
    for (int ma = 0; ma < 2; ma++) {
        int r = row0 + wy * 32 + ma * 16 + g;
#pragma unroll
        for (int na = 0; na < 8; na++) {
            int colb = wx * 64 + na * 8 + tg * 2;
            float b0 = 0.f, b1 = 0.f;
            if (flags & 1) { b0 = biasp[colb]; b1 = biasp[colb + 1]; }
            float v0 = c[ma][na][0] + b0, v1 = c[ma][na][1] + b1;
            float v2 = c[ma][na][2] + b0, v3 = c[ma][na][3] + b1;
            if (flags & 2) {
                v0 = fmaxf(v0, 0.f); v1 = fmaxf(v1, 0.f);
                v2 = fmaxf(v2, 0.f); v3 = fmaxf(v3, 0.f);
            }
            if (CH) {
                if (r < M)     *(__half2*)&Chh[(size_t)r * ldc + colb]       = __floats2half2_rn(v0, v1);
                if (r + 8 < M) *(__half2*)&Chh[(size_t)(r + 8) * ldc + colb] = __floats2half2_rn(v2, v3);
            } else {
                if (r < M)     *(float2*)&Cf[(size_t)r * ldc + colb]       = make_float2(v0, v1);
                if (r + 8 < M) *(float2*)&Cf[(size_t)(r + 8) * ldc + colb] = make_float2(v2, v3);
            }
        }
    }
#undef LOADG
#undef STS
}

// Regular GEMM: B may be a sequence of [K, bsplit] matrices (bsplit == ldb).
template<int AH, int CH>
__global__ void __launch_bounds__(256)
mm_gemm(const void* __restrict__ A, int lda, const __half* __restrict__ B, int ldb,
        int bsplit, const float* __restrict__ bias, void* __restrict__ C, int ldc,
        int M, int K, int flags) {
    int n0 = blockIdx.x * 128;
    int row0 = blockIdx.y * 128;
    const __half* Bp = B + (size_t)(n0 / bsplit) * K * bsplit + (n0 % bsplit);
    void* Cp = CH ? (void*)((__half*)C + n0) : (void*)((float*)C + n0);
    mm_core<AH, CH>(A, lda, row0, M, K, Bp, ldb,
                    (flags & 1) ? bias + n0 : nullptr, Cp, ldc, flags);
}

// GAT message GEMM: per (b,h): msg[j, d] = sum_i attn[b,h,j,i] * xp[b, i, h*256+d]
__global__ void __launch_bounds__(256)
mm_msg_gemm(const __half* __restrict__ attn, const __half* __restrict__ xp,
            __half* __restrict__ msgh) {
    int z = blockIdx.z;
    int b = z >> 3, h = z & 7;
    int n0 = blockIdx.x * 128;
    int row0 = blockIdx.y * 128;
    const __half* A = attn + (size_t)z * Nn * Nn;
    const __half* Bp = xp + (size_t)b * Nn * HPH + h * Hh + n0;
    __half* Cp = msgh + (size_t)b * Nn * HPH + h * Hh + n0;
    mm_core<1, 1>(A, Nn, row0, Nn, Nn, Bp, HPH, nullptr, Cp, HPH, 0);
}

// ============================================================================
// conversion helpers
// ============================================================================
__global__ void to_half(const float* __restrict__ src, __half* __restrict__ dst, int n) {
    int i = (blockIdx.x * 256 + threadIdx.x) * 4;
    if (i < n) {
        float4 v = *(const float4*)&src[i];
        *(__half2*)&dst[i] = __floats2half2_rn(v.x, v.y);
        *(__half2*)&dst[i + 2] = __floats2half2_rn(v.z, v.w);
    }
}
__global__ void conv_init(const float* __restrict__ src, float* __restrict__ dst,
                          __half* __restrict__ dsth) {
    int i = (blockIdx.x * 256 + threadIdx.x) * 4;
    float4 v = *(const float4*)&src[i];
    *(float4*)&dst[i] = v;
    *(__half2*)&dsth[i] = __floats2half2_rn(v.x, v.y);
    *(__half2*)&dsth[i + 2] = __floats2half2_rn(v.z, v.w);
}

// ============================================================================
// GAT coefficient / softmax / reduce
// ============================================================================
__global__ void gat_coef(const __half* __restrict__ xp, const float* __restrict__ att_src,
                         const float* __restrict__ att_dst, float* __restrict__ asrc,
                         float* __restrict__ adst, int g) {
    int row = blockIdx.x;
    int b = row / Nn, n = row % Nn;
    int h = threadIdx.x >> 5, lane = threadIdx.x & 31;
    const __half* xr = xp + (size_t)row * HPH + h * Hh;
    const float* as = att_src + (size_t)(g * NHh + h) * Hh;
    const float* ad = att_dst + (size_t)(g * NHh + h) * Hh;
    float s1 = 0.f, s2 = 0.f;
    for (int d = lane; d < Hh; d += 32) {
        float xv = __half2float(xr[d]);
        s1 += xv * as[d];
        s2 += xv * ad[d];
    }
    s1 = warp_sum(s1);
    s2 = warp_sum(s2);
    if (!lane) {
        asrc[(b * NHh + h) * Nn + n] = s1;
        adst[(b * NHh + h) * Nn + n] = s2;
    }
}

__global__ void gat_softmax(const float* __restrict__ asrc, const float* __restrict__ adst,
                            const int* __restrict__ adj, __half* __restrict__ attn) {
    int j = blockIdx.x, b = blockIdx.y;
    __shared__ float am[Nn];
    __shared__ float Ps[NHh][Nn];
    int tid = threadIdx.x;
    if (tid < Nn)
        am[tid] = (tid == j || adj[(b * Nn + tid) * Nn + j] > 0) ? 1.f : 0.f;
    __syncthreads();
    int h = tid >> 5, lane = tid & 31;
    float ad = adst[(b * NHh + h) * Nn + j];
    const float* as = asrc + (b * NHh + h) * Nn;
    __half* arow = attn + (size_t)((b * NHh + h) * Nn + j) * Nn;
    float m = -1e30f;
    for (int i = lane; i < Nn; i += 32) {
        float e = ad + as[i];
        e = e > 0.f ? e : 0.2f * e;        // leaky_relu(0.2)
        e = am[i] > 0.f ? e : -1e9f;
        Ps[h][i] = e;
        m = fmaxf(m, e);
    }
    m = warp_max(m);
    float s = 0.f;
    for (int i = lane; i < Nn; i += 32) {
        float e = __expf(Ps[h][i] - m);
        Ps[h][i] = e;
        s += e;
    }
    s = warp_sum(s);
    float inv = 1.f / s;
    for (int i = lane; i < Nn; i += 32) arow[i] = __float2half(Ps[h][i] * inv);
}

__global__ void gat_msg_reduce(const __half* __restrict__ msgh, const float* __restrict__ gbias,
                               int g, float* __restrict__ x, __half* __restrict__ xh) {
    int row = blockIdx.x, d = threadIdx.x;
    const __half* mr = msgh + (size_t)row * HPH;
    float s = 0.f;
#pragma unroll
    for (int h = 0; h < NHh; h++) s += __half2float(mr[h * Hh + d]);
    s = s * (1.f / NHh) + gbias[g * Hh + d];
    float nv = x[row * Hh + d] + fmaxf(s, 0.f);
    x[row * Hh + d] = nv;
    xh[row * Hh + d] = __float2half(nv);
}

// ============================================================================
// add + LayerNorm (writes fp32 + fp16)
// ============================================================================
__global__ void add_ln(const float* __restrict__ a, const float* __restrict__ bsrc,
                       float* __restrict__ outp, __half* __restrict__ outh,
                       const float* __restrict__ sb, int relu_b) {
    int row = blockIdx.x, d = threadIdx.x;
    float bv = bsrc[(size_t)row * Hh + d];
    if (relu_b) bv = fmaxf(bv, 0.f);
    float v = a[(size_t)row * Hh + d] + bv;
    __shared__ float sw[8], sw2[8];
    float s = warp_sum(v), s2 = warp_sum(v * v);
    int w = d >> 5, lane = d & 31;
    if (!lane) { sw[w] = s; sw2[w] = s2; }
    __syncthreads();
    float ts = 0.f, ts2 = 0.f;
#pragma unroll
    for (int i = 0; i < 8; i++) { ts += sw[i]; ts2 += sw2[i]; }
    float mean = ts * (1.f / Hh);
    float var = ts2 * (1.f / Hh) - mean * mean;
    float o = (v - mean) * rsqrtf(var + 1e-5f) * sb[d] + sb[Hh + d];
    outp[(size_t)row * Hh + d] = o;
    outh[(size_t)row * Hh + d] = __float2half(o);
}

// ============================================================================
// Fused masked MHA (reads fused qkv fp32 buffer [rows, 768], writes ctx half)
// ============================================================================
__global__ void mha_attn(const float* __restrict__ qkv, const int* __restrict__ adj,
                         __half* __restrict__ ctx) {
    int h = blockIdx.x, b = blockIdx.y;
    extern __shared__ float sm[];
    float* Qs = sm;
    float* Ks = Qs + Nn * 32;
    float* Vs = Ks + Nn * 33;
    float* Ps = Vs + Nn * 32;
    int tid = threadIdx.x;
    for (int idx = tid; idx < Nn * 32; idx += 256) {
        int i = idx >> 5, d = idx & 31;
        int gi = (b * Nn + i) * 768 + h * 32 + d;
        Qs[i * 32 + d] = qkv[gi];
        Ks[i * 33 + d] = qkv[gi + 256];
        Vs[i * 32 + d] = qkv[gi + 512];
    }
    __syncthreads();
    int w = tid >> 5, lane = tid & 31;
    float* P = Ps + w * Nn;
    const float scale = 0.17677669529663687f;   // 1/sqrt(32)
    for (int j = w; j < Nn; j += 8) {
        const float* qj = Qs + j * 32;
        const int* arow = adj + (b * Nn + j) * Nn;
        float m = -1e30f;
        for (int i = lane; i < Nn; i += 32) {
            const float* kr = Ks + i * 33;
            float s = 0.f;
#pragma unroll
            for (int d = 0; d < 32; d++) s += qj[d] * kr[d];
            s = arow[i] > 0 ? s * scale : -1e9f;
            P[i] = s;
            m = fmaxf(m, s);
        }
        m = warp_max(m);
        float sum = 0.f;
        for (int i = lane; i < Nn; i += 32) {
            float e = __expf(P[i] - m);
            P[i] = e;
            sum += e;
        }
        sum = warp_sum(sum);
        float inv = 1.f / sum;
        __syncwarp();
        float acc = 0.f;
        for (int i = 0; i < Nn; i++) acc += P[i] * Vs[i * 32 + lane];
        ctx[(b * Nn + j) * Hh + h * 32 + lane] = __float2half(acc * inv);
        __syncwarp();
    }
}

// ============================================================================
// LSTM cell
// ============================================================================
__global__ void lstm_kernel(const float* __restrict__ xin, const float* __restrict__ hin,
                            const float* __restrict__ cin, const float* __restrict__ Wih,
                            const float* __restrict__ Whh, const float* __restrict__ bias,
                            float* __restrict__ gh, float* __restrict__ gc,
                            float* __restrict__ out) {
    int b = blockIdx.x, tid = threadIdx.x;
    __shared__ float xs[Hh], hs[Hh], gsh[4 * Hh];
    xs[tid] = xin[b * Hh + tid];
    hs[tid] = hin[b * Hh + tid];
    __syncthreads();
    for (int r = tid; r < 4 * Hh; r += Hh) {
        const float* wi = Wih + (size_t)r * Hh;
        const float* wh = Whh + (size_t)r * Hh;
        float s = bias[r];
        for (int d = 0; d < Hh; d++) s += xs[d] * wi[d] + hs[d] * wh[d];
        gsh[r] = s;
    }
    __syncthreads();
    float ig = gsh[tid], fg = gsh[Hh + tid], gg = gsh[2 * Hh + tid], og = gsh[3 * Hh + tid];
    float c = sigmf(fg) * cin[b * Hh + tid] + sigmf(ig) * tanhf(gg);
    float hv = sigmf(og) * tanhf(c);
    gh[b * Hh + tid] = hv;
    gc[b * Hh + tid] = c;
    out[OUT_H + b * Hh + tid] = hv;
    out[OUT_C + b * Hh + tid] = c;
}

// ============================================================================
// Pointer head
// ============================================================================
__global__ void ptr_kernel(const float* __restrict__ refb, const float* __restrict__ qh,
                           const float* __restrict__ vvec, const int* __restrict__ mask,
                           float* __restrict__ out) {
    int b = blockIdx.x, tid = threadIdx.x;
    __shared__ float us[Nn];
    __shared__ float red[8];
    int w = tid >> 5, lane = tid & 31;
    const float* qv = qh + b * Hh;
    for (int n = w; n < Nn; n += 8) {
        const float* r = refb + (size_t)(b * Nn + n) * Hh;
        float s = 0.f;
        for (int d = lane; d < Hh; d += 32) s += tanhf(r[d] + qv[d]) * vvec[d];
        s = warp_sum(s);
        if (!lane) us[n] = s;
    }
    __syncthreads();
    float vvv = -1e30f;
    if (tid < Nn) vvv = mask[b * Nn + tid] > 0 ? us[tid] : -1e9f;
    float m = warp_max(vvv);
    if (!lane) red[w] = m;
    __syncthreads();
    float bm = red[0];
#pragma unroll
    for (int i = 1; i < 8; i++) bm = fmaxf(bm, red[i]);
    float e = (tid < Nn) ? __expf(vvv - bm) : 0.f;
    float s = warp_sum(e);
    __syncthreads();
    if (!lane) red[w] = s;
    __syncthreads();
    float bs = 0.f;
#pragma unroll
    for (int i = 0; i < 8; i++) bs += red[i];
    if (tid < Nn) out[OUT_POLICY + b * Nn + tid] = e / bs;
}

__global__ void copy_kernel(const float* __restrict__ src, float* __restrict__ dst) {
    int i = blockIdx.x * 256 + threadIdx.x;
    dst[i] = src[i];
}

// ============================================================================
// Launch
// ============================================================================
extern "C" void kernel_launch(void* const* d_in, const int* in_sizes, int n_in,
                              void* d_out, int out_size) {
    const float* enc        = (const float*)d_in[0];
    const float* dec_input  = (const float*)d_in[1];
    const float* dec_h      = (const float*)d_in[2];
    const float* dec_c      = (const float*)d_in[3];
    const float* gat_W      = (const float*)d_in[4];
    const float* gat_asrc_w = (const float*)d_in[5];
    const float* gat_adst_w = (const float*)d_in[6];
    const float* gat_bias   = (const float*)d_in[7];
    const float* gat_ln     = (const float*)d_in[8];
    const float* attn_W     = (const float*)d_in[9];
    const float* attn_b     = (const float*)d_in[10];
    const float* ln1        = (const float*)d_in[11];
    const float* ffn_W1     = (const float*)d_in[12];
    const float* ffn_b1     = (const float*)d_in[13];
    const float* ffn_W2     = (const float*)d_in[14];
    const float* ffn_b2     = (const float*)d_in[15];
    const float* ln2        = (const float*)d_in[16];
    const float* lstm_Wih   = (const float*)d_in[17];
    const float* lstm_Whh   = (const float*)d_in[18];
    const float* lstm_b     = (const float*)d_in[19];
    const float* ptr_Wref   = (const float*)d_in[20];
    const float* ptr_Wq     = (const float*)d_in[21];
    const float* ptr_v      = (const float*)d_in[22];
    const int*   adj        = (const int*)d_in[23];
    const int*   mask       = (const int*)d_in[24];
    float* out = (float*)d_out;

    float* S = nullptr;
    cudaGetSymbolAddress((void**)&S, g_scratch);
    __half* H = nullptr;
    cudaGetSymbolAddress((void**)&H, g_hscratch);

    float* x    = S + OFF_X;
    float* asrc = S + OFF_ASRC;
    float* adst = S + OFF_ADST;
    float* emb  = S + OFF_EMB;
    float* qkv  = S + OFF_QKV;
    float* tmp  = S + OFF_TMP;
    float* refb = S + OFF_REF;
    float* gh   = S + OFF_HB;
    float* gc   = S + OFF_CB;
    float* qh   = S + OFF_QH;

    __half* xph   = H + HS_XPH;
    __half* attnh = H + HS_ATTNH;
    __half* msghh = H + HS_MSGH;
    __half* xh    = H + HS_XH;
    __half* embh  = H + HS_EMBH;
    __half* ctxh  = H + HS_CTXH;
    __half* t1h   = H + HS_T1H;
    __half* wGat  = H + HW_GAT;
    __half* wAttn = H + HW_ATTN;
    __half* wF1   = H + HW_FFN1;
    __half* wF2   = H + HW_FFN2;
    __half* wPref = H + HW_PREF;
    __half* wPq   = H + HW_PQ;

    cudaFuncSetAttribute(mha_attn, cudaFuncAttributeMaxDynamicSharedMemorySize, 84000);

    // weight conversions (once per launch)
    to_half<<<1024, 256>>>(gat_W, wGat, 2 * Hh * HPH);
    to_half<<<768, 256>>>(attn_W, wAttn, Ll * 4 * Hh * Hh);
    to_half<<<384, 256>>>(ffn_W1, wF1, Ll * Hh * Ff);
    to_half<<<384, 256>>>(ffn_W2, wF2, Ll * Ff * Hh);
    to_half<<<64, 256>>>(ptr_Wref, wPref, Hh * Hh);
    to_half<<<64, 256>>>(ptr_Wq, wPq, Hh * Hh);

    // x = enc (fp32 + half)
    conv_init<<<3200, 256>>>(enc, x, xh);

    // ---- GAT stack ----
    for (int g = 0; g < Gg; g++) {
        mm_gemm<1, 1><<<dim3(16, 100), 256>>>(xh, Hh, wGat + (size_t)g * Hh * HPH,
                                              HPH, HPH, nullptr, xph, HPH, ROWS, Hh, 0);
        gat_coef<<<ROWS, 256>>>(xph, gat_asrc_w, gat_adst_w, asrc, adst, g);
        gat_softmax<<<dim3(Nn, Bb), 256>>>(asrc, adst, adj, attnh);
        mm_msg_gemm<<<dim3(2, 2, 512), 256>>>(attnh, xph, msghh);
        gat_msg_reduce<<<ROWS, Hh>>>(msghh, gat_bias, g, x, xh);
    }
    add_ln<<<ROWS, Hh>>>(enc, x, emb, embh, gat_ln, 1);

    // ---- Transformer encoder ----
    for (int l = 0; l < Ll; l++) {
        const __half* W = wAttn + (size_t)l * 4 * Hh * Hh;
        const float* bq = attn_b + (size_t)l * 4 * Hh;
        // fused QKV: N=768, B = 3 consecutive [256,256] half matrices
        mm_gemm<1, 0><<<dim3(6, 100), 256>>>(embh, Hh, W, Hh, Hh, bq, qkv, 768, ROWS, Hh, 1);
        mha_attn<<<dim3(NHh, Bb), 256, 84000>>>(qkv, adj, ctxh);
        mm_gemm<1, 0><<<dim3(2, 100), 256>>>(ctxh, Hh, W + 3 * Hh * Hh, Hh, Hh,
                                             bq + 3 * Hh, tmp, Hh, ROWS, Hh, 1);
        add_ln<<<ROWS, Hh>>>(emb, tmp, emb, embh, ln1 + (size_t)l * 2 * Hh, 0);
        mm_gemm<1, 1><<<dim3(4, 100), 256>>>(embh, Hh, wF1 + (size_t)l * Hh * Ff, Ff, Ff,
                                             ffn_b1 + (size_t)l * Ff, t1h, Ff, ROWS, Hh, 3);
        mm_gemm<1, 0><<<dim3(2, 100), 256>>>(t1h, Ff, wF2 + (size_t)l * Ff * Hh, Hh, Hh,
                                             ffn_b2 + (size_t)l * Hh, tmp, Hh, ROWS, Ff, 1);
        add_ln<<<ROWS, Hh>>>(emb, tmp, emb, embh, ln2 + (size_t)l * 2 * Hh, 0);
    }

    // ---- LSTM cell + pointer head ----
    lstm_kernel<<<Bb, Hh>>>(dec_input, dec_h, dec_c, lstm_Wih, lstm_Whh, lstm_b, gh, gc, out);
    mm_gemm<1, 0><<<dim3(2, 100), 256>>>(embh, Hh, wPref, Hh, Hh, nullptr, refb, Hh, ROWS, Hh, 0);
    mm_gemm<0, 0><<<dim3(2, 1), 256>>>(gh, Hh, wPq, Hh, Hh, nullptr, qh, Hh, Bb, Hh, 0);
    ptr_kernel<<<Bb, 256>>>(refb, qh, ptr_v, mask, out);

    // ---- emit emb ----
    copy_kernel<<<12800, 256>>>(emb, out + OUT_EMB);
}